// round 6
// baseline (speedup 1.0000x reference)
#include <cuda_runtime.h>
#include <math.h>

#define NN 50000
#define EE 400000
#define DD 128
#define HH 256

// ---------------- scratch (static device globals; referenced ONLY from device code) ----
__device__ float g_h1 [NN * HH];          // enc1 output, later reused as decoder hidden
__device__ float g_h  [NN * HH];          // enc2 output
__device__ float g_agg[NN * HH];          // sum_{src->dst} h[src]
__device__ float g_Bcat[HH * 2 * HH];     // [Wc | dec_w1b] as [H, 2H] row-major
__device__ float g_v  [HH];               // dec_w1a @ msg_b
__device__ int   g_deg [NN];
__device__ int   g_fill[NN];
__device__ int   g_rowptr[NN + 1];
__device__ int   g_esrc[EE];

// ---------------- init: zero degree / fill counters every launch ----------------
__global__ void zero_kernel() {
    int i = blockIdx.x * blockDim.x + threadIdx.x;
    if (i < NN) { g_deg[i] = 0; g_fill[i] = 0; }
}

// ---------------- fold msg GEMM into decoder weights ----------------
// Wc[i][k] = sum_j dec_w1[i][j] * msg_w[j][k];  v[i] = sum_j dec_w1[i][j] * msg_b[j]
// Bcat[i][0:H] = Wc[i], Bcat[i][H:2H] = dec_w1[i][H:2H]
__global__ void combine_kernel(const float* __restrict__ dec_w1,
                               const float* __restrict__ msg_w,
                               const float* __restrict__ msg_b) {
    int i = blockIdx.x;     // 0..255
    int k = threadIdx.x;    // 0..255
    __shared__ float srow[HH];
    srow[k] = dec_w1[i * 2 * HH + k];
    __syncthreads();
    float sum = 0.f;
    #pragma unroll 8
    for (int j = 0; j < HH; j++)
        sum = fmaf(srow[j], msg_w[j * HH + k], sum);
    g_Bcat[i * 2 * HH + k]      = sum;
    g_Bcat[i * 2 * HH + HH + k] = dec_w1[i * 2 * HH + HH + k];

    __shared__ float red[HH];
    red[k] = srow[k] * msg_b[k];
    __syncthreads();
    for (int off = HH / 2; off > 0; off >>= 1) {
        if (k < off) red[k] += red[k + off];
        __syncthreads();
    }
    if (k == 0) g_v[i] = red[0];
}

// ---------------- CSR build (edge_index is int32: src = ei[e], dst = ei[EE+e]) ------
__global__ void hist_kernel(const int* __restrict__ ei) {
    int e = blockIdx.x * blockDim.x + threadIdx.x;
    if (e < EE) {
        int dd = ei[EE + e];
        if (dd >= 0 && dd < NN) atomicAdd(&g_deg[dd], 1);
    }
}

__global__ void scan_kernel() {   // single block, 1024 threads
    const int CH = (NN + 1023) / 1024;   // 49 -> covers 50176 >= NN+1
    int t = threadIdx.x;
    int base = t * CH;
    int sum = 0;
    for (int i = base; i < base + CH; i++)
        if (i < NN) sum += g_deg[i];
    __shared__ int sm[1024];
    sm[t] = sum;
    __syncthreads();
    for (int off = 1; off < 1024; off <<= 1) {
        int vv = (t >= off) ? sm[t - off] : 0;
        __syncthreads();
        sm[t] += vv;
        __syncthreads();
    }
    int run = sm[t] - sum;   // exclusive prefix for this chunk
    for (int i = base; i < base + CH; i++) {
        if (i <= NN) g_rowptr[i] = run;
        if (i < NN)  run += g_deg[i];
    }
}

__global__ void scatter_kernel(const int* __restrict__ ei) {
    int e = blockIdx.x * blockDim.x + threadIdx.x;
    if (e < EE) {
        int dd = ei[EE + e];
        if (dd >= 0 && dd < NN) {
            int pos = g_rowptr[dd] + atomicAdd(&g_fill[dd], 1);
            g_esrc[pos] = ei[e];
        }
    }
}

// ---------------- aggregation: warp per node, L2-resident gather-sum ----------------
__global__ void aggregate_kernel() {
    int warp = (blockIdx.x * blockDim.x + threadIdx.x) >> 5;
    int lane = threadIdx.x & 31;
    if (warp >= NN) return;
    int s0 = g_rowptr[warp], s1 = g_rowptr[warp + 1];
    float4 acc0 = make_float4(0.f, 0.f, 0.f, 0.f);
    float4 acc1 = make_float4(0.f, 0.f, 0.f, 0.f);
    for (int e = s0; e < s1; e++) {
        const float4* r = (const float4*)(g_h + (size_t)g_esrc[e] * HH);
        float4 x0 = __ldg(&r[lane]);
        float4 x1 = __ldg(&r[lane + 32]);
        acc0.x += x0.x; acc0.y += x0.y; acc0.z += x0.z; acc0.w += x0.w;
        acc1.x += x1.x; acc1.y += x1.y; acc1.z += x1.z; acc1.w += x1.w;
    }
    float4* o = (float4*)(g_agg + (size_t)warp * HH);
    o[lane]      = acc0;
    o[lane + 32] = acc1;
}

// ---------------- fused SGEMM (NT): C = act(A @ B^T + bias [+ deg*v]) ----------------
// ASEL: 0 = Aparam (K=128), 1 = g_h1 (K=256), 2 = dual [g_agg | g_h] (K=512)
// BSEL: 0 = Bparam, 1 = g_Bcat
// CSEL: 0 = Cparam, 1 = g_h1, 2 = g_h
// BM=BN=128, BK=8, 256 threads, 8x8 per thread, global->register prefetch.
template<int ACT, int ASEL, int BSEL, int CSEL, int DEG>
__global__ void __launch_bounds__(256, 2)
sgemm_kernel(const float* __restrict__ Aparam, const float* __restrict__ Bparam,
             int K, const float* __restrict__ bias,
             float* __restrict__ Cparam, int M, int Nout)
{
    const float* A;
    const float* A2 = nullptr;
    int KA;
    if (ASEL == 0)      { A = Aparam; KA = DD; }
    else if (ASEL == 1) { A = g_h1;   KA = HH; }
    else                { A = g_agg;  A2 = g_h; KA = HH; }
    const float* B = (BSEL == 0) ? Bparam : g_Bcat;
    float* C = (CSEL == 0) ? Cparam : ((CSEL == 1) ? g_h1 : g_h);

    __shared__ float As[8][128];
    __shared__ float Bs[8][128];
    const int tid  = threadIdx.x;
    const int bm   = blockIdx.y * 128;
    const int bn   = blockIdx.x * 128;
    const int lrow = tid >> 1;          // 0..127
    const int lk   = (tid & 1) * 4;     // 0 or 4
    const int tx   = (tid & 15) * 8;    // col in tile
    const int ty   = (tid >> 4) * 8;    // row in tile

    float acc[8][8];
    #pragma unroll
    for (int i = 0; i < 8; i++)
        #pragma unroll
        for (int j = 0; j < 8; j++) acc[i][j] = 0.f;

    const int grow = bm + lrow;
    const int brow = bn + lrow;

    // prefetch first tile into registers
    float4 av = make_float4(0.f, 0.f, 0.f, 0.f);
    float4 bv;
    if (grow < M) av = *(const float4*)(A + (size_t)grow * KA + lk);
    bv = *(const float4*)(B + (size_t)brow * K + lk);

    for (int kt = 0; kt < K; kt += 8) {
        __syncthreads();
        As[lk + 0][lrow] = av.x; As[lk + 1][lrow] = av.y;
        As[lk + 2][lrow] = av.z; As[lk + 3][lrow] = av.w;
        Bs[lk + 0][lrow] = bv.x; Bs[lk + 1][lrow] = bv.y;
        Bs[lk + 2][lrow] = bv.z; Bs[lk + 3][lrow] = bv.w;
        __syncthreads();

        int kn = kt + 8;
        if (kn < K) {   // prefetch next tile while computing
            const float* Asrc = A; int kc = kn;
            if (ASEL == 2 && kn >= KA) { Asrc = A2; kc = kn - KA; }
            av = make_float4(0.f, 0.f, 0.f, 0.f);
            if (grow < M) av = *(const float4*)(Asrc + (size_t)grow * KA + kc + lk);
            bv = *(const float4*)(B + (size_t)brow * K + kn + lk);
        }

        #pragma unroll
        for (int k = 0; k < 8; k++) {
            float a[8], b[8];
            *(float4*)&a[0] = *(const float4*)&As[k][ty];
            *(float4*)&a[4] = *(const float4*)&As[k][ty + 4];
            *(float4*)&b[0] = *(const float4*)&Bs[k][tx];
            *(float4*)&b[4] = *(const float4*)&Bs[k][tx + 4];
            #pragma unroll
            for (int i = 0; i < 8; i++)
                #pragma unroll
                for (int j = 0; j < 8; j++)
                    acc[i][j] = fmaf(a[i], b[j], acc[i][j]);
        }
    }

    // epilogue
    float bb[8], vv[8];
    #pragma unroll
    for (int j = 0; j < 8; j++) {
        bb[j] = bias[bn + tx + j];
        vv[j] = DEG ? g_v[bn + tx + j] : 0.f;
    }
    #pragma unroll
    for (int i = 0; i < 8; i++) {
        int row = bm + ty + i;
        if (row < M) {
            float dg = DEG ? (float)g_deg[row] : 0.f;
            float outv[8];
            #pragma unroll
            for (int j = 0; j < 8; j++) {
                float val = acc[i][j] + bb[j] + dg * vv[j];
                if (ACT == 1) val = fmaxf(val, 0.f);
                if (ACT == 2) val = tanhf(val);
                outv[j] = val;
            }
            *(float4*)(C + (size_t)row * Nout + bn + tx)     = *(float4*)&outv[0];
            *(float4*)(C + (size_t)row * Nout + bn + tx + 4) = *(float4*)&outv[4];
        }
    }
}

// ---------------- launch: ONLY plain kernel launches (graph-capturable) ----------------
extern "C" void kernel_launch(void* const* d_in, const int* in_sizes, int n_in,
                              void* d_out, int out_size) {
    (void)in_sizes; (void)n_in; (void)out_size;
    const float* x      = (const float*)d_in[0];
    const int*   ei     = (const int*)d_in[1];   // int32 (JAX canonicalizes int64->int32)
    // d_in[2] = steps (static 1 for this problem)
    const float* enc_w1 = (const float*)d_in[3];
    const float* enc_b1 = (const float*)d_in[4];
    const float* enc_w2 = (const float*)d_in[5];
    const float* enc_b2 = (const float*)d_in[6];
    const float* msg_w  = (const float*)d_in[7];
    const float* msg_b  = (const float*)d_in[8];
    const float* dec_w1 = (const float*)d_in[9];
    const float* dec_b1 = (const float*)d_in[10];
    const float* dec_w2 = (const float*)d_in[11];
    const float* dec_b2 = (const float*)d_in[12];
    float* out = (float*)d_out;

    zero_kernel<<<(NN + 255) / 256, 256>>>();
    combine_kernel<<<HH, HH>>>(dec_w1, msg_w, msg_b);
    hist_kernel<<<(EE + 255) / 256, 256>>>(ei);
    scan_kernel<<<1, 1024>>>();
    scatter_kernel<<<(EE + 255) / 256, 256>>>(ei);

    dim3 gH(HH / 128, (NN + 127) / 128);   // Nout = 256
    dim3 gD(DD / 128, (NN + 127) / 128);   // Nout = 128

    // enc1: g_h1 = relu(x @ enc_w1^T + b1), K=128
    sgemm_kernel<1, 0, 0, 1, 0><<<gH, 256>>>(x, enc_w1, DD, enc_b1, nullptr, NN, HH);
    // enc2: g_h = relu(g_h1 @ enc_w2^T + b2), K=256
    sgemm_kernel<1, 1, 0, 2, 0><<<gH, 256>>>(nullptr, enc_w2, HH, enc_b2, nullptr, NN, HH);
    // agg = sum_{edges} h[src]
    aggregate_kernel<<<(NN * 32 + 255) / 256, 256>>>();
    // dec1: g_h1 (reused) = relu(agg @ Wc^T + h @ dec_w1b^T + deg*v + b1), K=512 dual-A
    sgemm_kernel<1, 2, 1, 1, 1><<<gH, 256>>>(nullptr, nullptr, 2 * HH, dec_b1, nullptr, NN, HH);
    // dec2: out = tanh(g_h1 @ dec_w2^T + b2), K=256, Nout=128
    sgemm_kernel<2, 1, 0, 0, 0><<<gD, 256>>>(nullptr, dec_w2, HH, dec_b2, out, NN, DD);
}

// round 7
// speedup vs baseline: 1.1255x; 1.1255x over previous
#include <cuda_runtime.h>
#include <math.h>

#define NN 50000
#define EE 400000
#define DD 128
#define HH 256
#define NB 196   // ceil(NN/256)

// ---------------- scratch (static device globals) ----------------
__device__ float g_h1 [NN * HH];          // enc1 output, later reused as decoder hidden
__device__ float g_h  [NN * HH];          // enc2 output
__device__ float g_agg[NN * HH];          // sum_{src->dst} h[src]
__device__ float g_Bcat[HH * 2 * HH];     // [Wc | dec_w1b] as [H, 2H] row-major
__device__ float g_v  [HH];               // dec_w1a @ msg_b
__device__ int   g_deg [NN];
__device__ int   g_fill[NN];
__device__ int   g_rowptr[NN + 1];
__device__ int   g_esrc[EE];
__device__ int   g_bsum[NB];

// ---------------- f32x2 packed-fp32 helpers (Blackwell dual-rate FFMA2) -------------
__device__ __forceinline__ double pack2(float lo, float hi) {
    double r;
    asm("mov.b64 %0, {%1, %2};" : "=d"(r) : "f"(lo), "f"(hi));
    return r;
}
__device__ __forceinline__ void fma2(double& acc, double a, double b) {
    asm("fma.rn.f32x2 %0, %1, %2, %0;" : "+d"(acc) : "d"(a), "d"(b));
}
union F4D2 { float4 f; double2 d; };
union D2F2 { double d; float2 f; };

// ---------------- init ----------------
__global__ void zero_kernel() {
    int i = blockIdx.x * blockDim.x + threadIdx.x;
    if (i < NN) { g_deg[i] = 0; g_fill[i] = 0; }
}

// ---------------- fold msg GEMM into decoder weights ----------------
__global__ void combine_kernel(const float* __restrict__ dec_w1,
                               const float* __restrict__ msg_w,
                               const float* __restrict__ msg_b) {
    int i = blockIdx.x;     // 0..255
    int k = threadIdx.x;    // 0..255
    __shared__ float srow[HH];
    srow[k] = dec_w1[i * 2 * HH + k];
    __syncthreads();
    float sum = 0.f;
    #pragma unroll 8
    for (int j = 0; j < HH; j++)
        sum = fmaf(srow[j], msg_w[j * HH + k], sum);
    g_Bcat[i * 2 * HH + k]      = sum;
    g_Bcat[i * 2 * HH + HH + k] = dec_w1[i * 2 * HH + HH + k];

    __shared__ float red[HH];
    red[k] = srow[k] * msg_b[k];
    __syncthreads();
    for (int off = HH / 2; off > 0; off >>= 1) {
        if (k < off) red[k] += red[k + off];
        __syncthreads();
    }
    if (k == 0) g_v[i] = red[0];
}

// ---------------- CSR build (edge_index int32: src = ei[e], dst = ei[EE+e]) ---------
__global__ void hist_kernel(const int* __restrict__ ei) {
    int e = blockIdx.x * blockDim.x + threadIdx.x;
    if (e < EE) {
        int dd = ei[EE + e];
        if (dd >= 0 && dd < NN) atomicAdd(&g_deg[dd], 1);
    }
}

// 3-phase multi-block exclusive scan of g_deg -> g_rowptr
__global__ void scan1_kernel() {
    __shared__ int sm[256];
    int t = threadIdx.x;
    int idx = blockIdx.x * 256 + t;
    sm[t] = (idx < NN) ? g_deg[idx] : 0;
    __syncthreads();
    for (int off = 128; off > 0; off >>= 1) {
        if (t < off) sm[t] += sm[t + off];
        __syncthreads();
    }
    if (t == 0) g_bsum[blockIdx.x] = sm[0];
}
__global__ void scan2_kernel() {   // 1 block, 256 threads; NB <= 256
    int t = threadIdx.x;
    int v = (t < NB) ? g_bsum[t] : 0;
    __shared__ int sm[256];
    sm[t] = v;
    __syncthreads();
    for (int off = 1; off < 256; off <<= 1) {
        int u = (t >= off) ? sm[t - off] : 0;
        __syncthreads();
        sm[t] += u;
        __syncthreads();
    }
    if (t < NB) g_bsum[t] = sm[t] - v;   // exclusive
}
__global__ void scan3_kernel() {
    __shared__ int sm[256];
    int t = threadIdx.x;
    int idx = blockIdx.x * 256 + t;
    int v = (idx < NN) ? g_deg[idx] : 0;
    sm[t] = v;
    __syncthreads();
    for (int off = 1; off < 256; off <<= 1) {
        int u = (t >= off) ? sm[t - off] : 0;
        __syncthreads();
        sm[t] += u;
        __syncthreads();
    }
    if (idx <= NN) g_rowptr[idx] = g_bsum[blockIdx.x] + sm[t] - v;  // exclusive prefix
}

__global__ void scatter_kernel(const int* __restrict__ ei) {
    int e = blockIdx.x * blockDim.x + threadIdx.x;
    if (e < EE) {
        int dd = ei[EE + e];
        if (dd >= 0 && dd < NN) {
            int pos = g_rowptr[dd] + atomicAdd(&g_fill[dd], 1);
            g_esrc[pos] = ei[e];
        }
    }
}

// ---------------- aggregation: warp per node, L2-resident gather-sum ----------------
__global__ void aggregate_kernel() {
    int warp = (blockIdx.x * blockDim.x + threadIdx.x) >> 5;
    int lane = threadIdx.x & 31;
    if (warp >= NN) return;
    int s0 = g_rowptr[warp], s1 = g_rowptr[warp + 1];
    float4 acc0 = make_float4(0.f, 0.f, 0.f, 0.f);
    float4 acc1 = make_float4(0.f, 0.f, 0.f, 0.f);
    for (int e = s0; e < s1; e++) {
        const float4* r = (const float4*)(g_h + (size_t)g_esrc[e] * HH);
        float4 x0 = __ldg(&r[lane]);
        float4 x1 = __ldg(&r[lane + 32]);
        acc0.x += x0.x; acc0.y += x0.y; acc0.z += x0.z; acc0.w += x0.w;
        acc1.x += x1.x; acc1.y += x1.y; acc1.z += x1.z; acc1.w += x1.w;
    }
    float4* o = (float4*)(g_agg + (size_t)warp * HH);
    o[lane]      = acc0;
    o[lane + 32] = acc1;
}

// ---------------- fused SGEMM v2 (NT): C = act(A @ B^T + bias [+ deg*v]) ------------
// f32x2 packed-fp32 math, conflict-free shared mapping (tx*4 + 64-col groups).
// BM=128, BN = NCG*64 (NCG=4 -> 256, NCG=2 -> 128), BK=8, 256 threads.
// Thread tile: 8 rows x (NCG*4) cols.  C row stride == BN (full Nout per block col).
// ASEL: 0 = Aparam (KA=128), 1 = g_h1 (KA=256), 2 = dual [g_agg | g_h] (KA=256 each)
// BSEL: 0 = Bparam, 1 = g_Bcat
// CSEL: 0 = Cparam, 1 = g_h1, 2 = g_h
template<int ACT, int ASEL, int BSEL, int CSEL, int DEG, int NCG>
__global__ void __launch_bounds__(256, 1)
sgemm2_kernel(const float* __restrict__ Aparam, const float* __restrict__ Bparam,
              int K, const float* __restrict__ bias,
              float* __restrict__ Cparam, int M)
{
    constexpr int BN = NCG * 64;
    const float* A;
    const float* A2 = nullptr;
    int KA;
    if (ASEL == 0)      { A = Aparam; KA = DD; }
    else if (ASEL == 1) { A = g_h1;   KA = HH; }
    else                { A = g_agg;  A2 = g_h; KA = HH; }
    const float* B = (BSEL == 0) ? Bparam : g_Bcat;
    float* C = (CSEL == 0) ? Cparam : ((CSEL == 1) ? g_h1 : g_h);

    __shared__ float As[8][128];
    __shared__ float Bs[8][BN];

    const int tid  = threadIdx.x;
    const int bm   = blockIdx.y * 128;
    const int bn   = blockIdx.x * BN;
    const int lrow = tid >> 1;          // 0..127
    const int lk   = (tid & 1) * 4;     // 0 or 4
    const int tx4  = (tid & 15) * 4;    // col base within 64-col group (conflict-free)
    const int ty8  = (tid >> 4) * 8;    // row in tile

    double acc[8][2 * NCG];
    #pragma unroll
    for (int i = 0; i < 8; i++)
        #pragma unroll
        for (int j = 0; j < 2 * NCG; j++) acc[i][j] = 0.0;

    const int grow = bm + lrow;

    // prefetch first k-tile into registers
    float4 av = make_float4(0.f, 0.f, 0.f, 0.f);
    float4 bv0, bv1;
    if (grow < M) av = *(const float4*)(A + (size_t)grow * KA + lk);
    bv0 = *(const float4*)(B + (size_t)(bn + lrow) * K + lk);
    if (NCG == 4)
        bv1 = *(const float4*)(B + (size_t)(bn + lrow + 128) * K + lk);

    for (int kt = 0; kt < K; kt += 8) {
        __syncthreads();
        As[lk + 0][lrow] = av.x; As[lk + 1][lrow] = av.y;
        As[lk + 2][lrow] = av.z; As[lk + 3][lrow] = av.w;
        Bs[lk + 0][lrow] = bv0.x; Bs[lk + 1][lrow] = bv0.y;
        Bs[lk + 2][lrow] = bv0.z; Bs[lk + 3][lrow] = bv0.w;
        if (NCG == 4) {
            Bs[lk + 0][lrow + 128] = bv1.x; Bs[lk + 1][lrow + 128] = bv1.y;
            Bs[lk + 2][lrow + 128] = bv1.z; Bs[lk + 3][lrow + 128] = bv1.w;
        }
        __syncthreads();

        int kn = kt + 8;
        if (kn < K) {   // prefetch next tile while computing
            const float* Asrc = A; int kc = kn;
            if (ASEL == 2 && kn >= KA) { Asrc = A2; kc = kn - KA; }
            av = make_float4(0.f, 0.f, 0.f, 0.f);
            if (grow < M) av = *(const float4*)(Asrc + (size_t)grow * KA + kc + lk);
            bv0 = *(const float4*)(B + (size_t)(bn + lrow) * K + kn + lk);
            if (NCG == 4)
                bv1 = *(const float4*)(B + (size_t)(bn + lrow + 128) * K + kn + lk);
        }

        #pragma unroll
        for (int k = 0; k < 8; k++) {
            float a[8];
            *(float4*)&a[0] = *(const float4*)&As[k][ty8];
            *(float4*)&a[4] = *(const float4*)&As[k][ty8 + 4];
            double bd[2 * NCG];
            #pragma unroll
            for (int cg = 0; cg < NCG; cg++) {
                F4D2 u;
                u.f = *(const float4*)&Bs[k][tx4 + cg * 64];
                bd[2 * cg]     = u.d.x;
                bd[2 * cg + 1] = u.d.y;
            }
            #pragma unroll
            for (int i = 0; i < 8; i++) {
                double ad = pack2(a[i], a[i]);
                #pragma unroll
                for (int j = 0; j < 2 * NCG; j++)
                    fma2(acc[i][j], ad, bd[j]);
            }
        }
    }

    // epilogue
    float bb[NCG][4], vv[NCG][4];
    #pragma unroll
    for (int cg = 0; cg < NCG; cg++) {
        *(float4*)&bb[cg][0] = *(const float4*)&bias[bn + tx4 + cg * 64];
        if (DEG) *(float4*)&vv[cg][0] = *(const float4*)&g_v[bn + tx4 + cg * 64];
    }
    #pragma unroll
    for (int i = 0; i < 8; i++) {
        int row = bm + ty8 + i;
        if (row < M) {
            float dg = DEG ? (float)g_deg[row] : 0.f;
            #pragma unroll
            for (int cg = 0; cg < NCG; cg++) {
                D2F2 p0, p1;
                p0.d = acc[i][2 * cg];
                p1.d = acc[i][2 * cg + 1];
                float4 o;
                o.x = p0.f.x + bb[cg][0]; o.y = p0.f.y + bb[cg][1];
                o.z = p1.f.x + bb[cg][2]; o.w = p1.f.y + bb[cg][3];
                if (DEG) {
                    o.x += dg * vv[cg][0]; o.y += dg * vv[cg][1];
                    o.z += dg * vv[cg][2]; o.w += dg * vv[cg][3];
                }
                if (ACT == 1) {
                    o.x = fmaxf(o.x, 0.f); o.y = fmaxf(o.y, 0.f);
                    o.z = fmaxf(o.z, 0.f); o.w = fmaxf(o.w, 0.f);
                }
                if (ACT == 2) {
                    o.x = tanhf(o.x); o.y = tanhf(o.y);
                    o.z = tanhf(o.z); o.w = tanhf(o.w);
                }
                *(float4*)(C + (size_t)row * BN + bn + tx4 + cg * 64) = o;
            }
        }
    }
}

// ---------------- launch: ONLY plain kernel launches (graph-capturable) -------------
extern "C" void kernel_launch(void* const* d_in, const int* in_sizes, int n_in,
                              void* d_out, int out_size) {
    (void)in_sizes; (void)n_in; (void)out_size;
    const float* x      = (const float*)d_in[0];
    const int*   ei     = (const int*)d_in[1];   // int32 (JAX canonicalizes int64->int32)
    const float* enc_w1 = (const float*)d_in[3];
    const float* enc_b1 = (const float*)d_in[4];
    const float* enc_w2 = (const float*)d_in[5];
    const float* enc_b2 = (const float*)d_in[6];
    const float* msg_w  = (const float*)d_in[7];
    const float* msg_b  = (const float*)d_in[8];
    const float* dec_w1 = (const float*)d_in[9];
    const float* dec_b1 = (const float*)d_in[10];
    const float* dec_w2 = (const float*)d_in[11];
    const float* dec_b2 = (const float*)d_in[12];
    float* out = (float*)d_out;

    zero_kernel<<<(NN + 255) / 256, 256>>>();
    combine_kernel<<<HH, HH>>>(dec_w1, msg_w, msg_b);
    hist_kernel<<<(EE + 255) / 256, 256>>>(ei);
    scan1_kernel<<<NB, 256>>>();
    scan2_kernel<<<1, 256>>>();
    scan3_kernel<<<NB, 256>>>();
    scatter_kernel<<<(EE + 255) / 256, 256>>>(ei);

    dim3 g256(1, (NN + 127) / 128);   // BN=256 GEMMs
    dim3 g128(1, (NN + 127) / 128);   // BN=128 GEMM (dec2)

    // enc1: g_h1 = relu(x @ enc_w1^T + b1), K=128
    sgemm2_kernel<1, 0, 0, 1, 0, 4><<<g256, 256>>>(x, enc_w1, DD, enc_b1, nullptr, NN);
    // enc2: g_h = relu(g_h1 @ enc_w2^T + b2), K=256
    sgemm2_kernel<1, 1, 0, 2, 0, 4><<<g256, 256>>>(nullptr, enc_w2, HH, enc_b2, nullptr, NN);
    // agg = sum_{edges} h[src]
    aggregate_kernel<<<(NN * 32 + 255) / 256, 256>>>();
    // dec1: g_h1 (reused) = relu(agg @ Wc^T + h @ dec_w1b^T + deg*v + b1), K=512 dual-A
    sgemm2_kernel<1, 2, 1, 1, 1, 4><<<g256, 256>>>(nullptr, nullptr, 2 * HH, dec_b1, nullptr, NN);
    // dec2: out = tanh(g_h1 @ dec_w2^T + b2), K=256, Nout=128
    sgemm2_kernel<2, 1, 0, 0, 0, 2><<<g128, 256>>>(nullptr, dec_w2, HH, dec_b2, out, NN);
}

// round 9
// speedup vs baseline: 1.4713x; 1.3072x over previous
#include <cuda_runtime.h>
#include <cuda_bf16.h>
#include <cstdint>
#include <math.h>

#define NN 50000
#define EE 400000
#define DD 128
#define HH 256
#define NB 196   // ceil(NN/256)

// ---------------- scratch (static device globals) ----------------
__device__ float g_h1 [NN * HH];          // enc1 output, later reused as decoder hidden
__device__ float g_h  [NN * HH];          // enc2 output
__device__ float g_agg[NN * HH];          // sum_{src->dst} h[src]
__device__ float g_Bcat[HH * 2 * HH];     // [Wc | dec_w1b] as [H, 2H] row-major
__device__ float g_v  [HH];               // dec_w1a @ msg_b
__device__ int   g_deg [NN];
__device__ int   g_fill[NN];
__device__ int   g_rowptr[NN + 1];
__device__ int   g_esrc[EE];
__device__ int   g_bsum[NB];

// ---------------- helpers ----------------
__device__ __forceinline__ uint32_t smem_u32(const void* p) {
    uint32_t a;
    asm("{ .reg .u64 t; cvta.to.shared.u64 t, %1; cvt.u32.u64 %0, t; }" : "=r"(a) : "l"(p));
    return a;
}
#define SWZ(off) ((off) ^ (((off) >> 3) & 0x70))

__device__ __forceinline__ void ldsm4(uint32_t* r, uint32_t addr) {
    asm volatile("ldmatrix.sync.aligned.m8n8.x4.shared.b16 {%0,%1,%2,%3}, [%4];"
                 : "=r"(r[0]), "=r"(r[1]), "=r"(r[2]), "=r"(r[3]) : "r"(addr));
}
__device__ __forceinline__ void mma_bf16(float* c, const uint32_t* a,
                                         uint32_t b0, uint32_t b1) {
    asm volatile(
        "mma.sync.aligned.m16n8k16.row.col.f32.bf16.bf16.f32 "
        "{%0,%1,%2,%3}, {%4,%5,%6,%7}, {%8,%9}, {%0,%1,%2,%3};"
        : "+f"(c[0]), "+f"(c[1]), "+f"(c[2]), "+f"(c[3])
        : "r"(a[0]), "r"(a[1]), "r"(a[2]), "r"(a[3]), "r"(b0), "r"(b1));
}

__device__ __forceinline__ uint32_t pk_bf2(float x, float y) {
    __nv_bfloat162 p = __floats2bfloat162_rn(x, y);
    return *reinterpret_cast<uint32_t*>(&p);
}
// split 8 fp32 into hi/lo bf16x2 uint4s
__device__ __forceinline__ void cvt8(const float4 f0, const float4 f1,
                                     uint4& uh, uint4& ul) {
    float a[8] = {f0.x, f0.y, f0.z, f0.w, f1.x, f1.y, f1.z, f1.w};
    float h[8], l[8];
    #pragma unroll
    for (int i = 0; i < 8; i++) {
        __nv_bfloat16 b = __float2bfloat16_rn(a[i]);
        h[i] = __bfloat162float(b);
        l[i] = a[i] - h[i];
    }
    uh = make_uint4(pk_bf2(h[0], h[1]), pk_bf2(h[2], h[3]),
                    pk_bf2(h[4], h[5]), pk_bf2(h[6], h[7]));
    ul = make_uint4(pk_bf2(l[0], l[1]), pk_bf2(l[2], l[3]),
                    pk_bf2(l[4], l[5]), pk_bf2(l[6], l[7]));
}

// ---------------- init ----------------
__global__ void zero_kernel() {
    int i = blockIdx.x * blockDim.x + threadIdx.x;
    if (i < NN) { g_deg[i] = 0; g_fill[i] = 0; }
}

// ---------------- fold msg GEMM into decoder weights ----------------
__global__ void combine_kernel(const float* __restrict__ dec_w1,
                               const float* __restrict__ msg_w,
                               const float* __restrict__ msg_b) {
    int i = blockIdx.x;
    int k = threadIdx.x;
    __shared__ float srow[HH];
    srow[k] = dec_w1[i * 2 * HH + k];
    __syncthreads();
    float sum = 0.f;
    #pragma unroll 8
    for (int j = 0; j < HH; j++)
        sum = fmaf(srow[j], msg_w[j * HH + k], sum);
    g_Bcat[i * 2 * HH + k]      = sum;
    g_Bcat[i * 2 * HH + HH + k] = dec_w1[i * 2 * HH + HH + k];

    __shared__ float red[HH];
    red[k] = srow[k] * msg_b[k];
    __syncthreads();
    for (int off = HH / 2; off > 0; off >>= 1) {
        if (k < off) red[k] += red[k + off];
        __syncthreads();
    }
    if (k == 0) g_v[i] = red[0];
}

// ---------------- CSR build ----------------
__global__ void hist_kernel(const int* __restrict__ ei) {
    int e = blockIdx.x * blockDim.x + threadIdx.x;
    if (e < EE) {
        int dd = ei[EE + e];
        if (dd >= 0 && dd < NN) atomicAdd(&g_deg[dd], 1);
    }
}
__global__ void scan1_kernel() {
    __shared__ int sm[256];
    int t = threadIdx.x;
    int idx = blockIdx.x * 256 + t;
    sm[t] = (idx < NN) ? g_deg[idx] : 0;
    __syncthreads();
    for (int off = 128; off > 0; off >>= 1) {
        if (t < off) sm[t] += sm[t + off];
        __syncthreads();
    }
    if (t == 0) g_bsum[blockIdx.x] = sm[0];
}
__global__ void scan2_kernel() {
    int t = threadIdx.x;
    int v = (t < NB) ? g_bsum[t] : 0;
    __shared__ int sm[256];
    sm[t] = v;
    __syncthreads();
    for (int off = 1; off < 256; off <<= 1) {
        int u = (t >= off) ? sm[t - off] : 0;
        __syncthreads();
        sm[t] += u;
        __syncthreads();
    }
    if (t < NB) g_bsum[t] = sm[t] - v;
}
__global__ void scan3_kernel() {
    __shared__ int sm[256];
    int t = threadIdx.x;
    int idx = blockIdx.x * 256 + t;
    int v = (idx < NN) ? g_deg[idx] : 0;
    sm[t] = v;
    __syncthreads();
    for (int off = 1; off < 256; off <<= 1) {
        int u = (t >= off) ? sm[t - off] : 0;
        __syncthreads();
        sm[t] += u;
        __syncthreads();
    }
    if (idx <= NN) g_rowptr[idx] = g_bsum[blockIdx.x] + sm[t] - v;
}
__global__ void scatter_kernel(const int* __restrict__ ei) {
    int e = blockIdx.x * blockDim.x + threadIdx.x;
    if (e < EE) {
        int dd = ei[EE + e];
        if (dd >= 0 && dd < NN) {
            int pos = g_rowptr[dd] + atomicAdd(&g_fill[dd], 1);
            g_esrc[pos] = ei[e];
        }
    }
}

// ---------------- aggregation: warp per node, L2-resident gather-sum ----------------
__global__ void aggregate_kernel() {
    int warp = (blockIdx.x * blockDim.x + threadIdx.x) >> 5;
    int lane = threadIdx.x & 31;
    if (warp >= NN) return;
    int s0 = g_rowptr[warp], s1 = g_rowptr[warp + 1];
    float4 acc0 = make_float4(0.f, 0.f, 0.f, 0.f);
    float4 acc1 = make_float4(0.f, 0.f, 0.f, 0.f);
    for (int e = s0; e < s1; e++) {
        const float4* r = (const float4*)(g_h + (size_t)g_esrc[e] * HH);
        float4 x0 = __ldg(&r[lane]);
        float4 x1 = __ldg(&r[lane + 32]);
        acc0.x += x0.x; acc0.y += x0.y; acc0.z += x0.z; acc0.w += x0.w;
        acc1.x += x1.x; acc1.y += x1.y; acc1.z += x1.z; acc1.w += x1.w;
    }
    float4* o = (float4*)(g_agg + (size_t)warp * HH);
    o[lane]      = acc0;
    o[lane + 32] = acc1;
}

// ========== bf16-split tensor GEMM via mma.sync: C = act(A @ B^T + bias [+deg*v]) ====
// Block 128x128, 256 threads = 8 warps (warp tile 32x64, grid 4M x 2N).
// K-chunks of 64 staged in SMEM as bf16 hi/lo (SW128 swizzle).
// 3-term split: C = Ah.Bh + Ah.Bl + Al.Bh  (fp32 accumulation).
// ASEL: 0 = Aparam (KA=128), 1 = g_h1 (KA=256), 2 = dual [g_agg | g_h]
// BSEL: 0 = Bparam, 1 = g_Bcat ; CSEL: 0 = Cparam, 1 = g_h1, 2 = g_h
template<int ACT, int ASEL, int BSEL, int CSEL, int DEG, int NOUT>
__global__ void __launch_bounds__(256, 1)
mm_gemm(const float* __restrict__ Aparam, const float* __restrict__ Bparam,
        int K, const float* __restrict__ bias, float* __restrict__ Cparam, int M)
{
    constexpr int OFF_AH = 0;
    constexpr int OFF_AL = 16384;
    constexpr int OFF_BH = 32768;
    constexpr int OFF_BL = 49152;

    extern __shared__ char smem[];
    const uint32_t sb = smem_u32(smem);
    const int tid  = threadIdx.x;
    const int wid  = tid >> 5;
    const int lane = tid & 31;
    const int wm   = wid & 3;     // M warp group: rows wm*32
    const int wn   = wid >> 2;    // N warp group: cols wn*64

    const float* A;
    const float* A2 = nullptr;
    int KA;
    if (ASEL == 0)      { A = Aparam; KA = DD; }
    else if (ASEL == 1) { A = g_h1;   KA = HH; }
    else                { A = g_agg;  A2 = g_h; KA = HH; }
    const float* Bm = (BSEL == 0) ? Bparam : g_Bcat;
    float* C = (CSEL == 0) ? Cparam : ((CSEL == 1) ? g_h1 : g_h);

    const int bm = blockIdx.x * 128;
    const int bn = blockIdx.y * 128;

    float acc[2][8][4];
    #pragma unroll
    for (int mg = 0; mg < 2; mg++)
        #pragma unroll
        for (int nt = 0; nt < 8; nt++)
            #pragma unroll
            for (int q = 0; q < 4; q++) acc[mg][nt][q] = 0.f;

    const int lrow = tid & 127;
    const int half = tid >> 7;           // col half 0/1 -> cols 0-31 / 32-63
    const int grow = bm + lrow;

    for (int kc = 0; kc < K; kc += 64) {
        // ---- stage + split A chunk [128 x 64] ----
        const float* Asrc = A;
        int kcc = kc;
        if (ASEL == 2 && kc >= KA) { Asrc = A2; kcc = kc - KA; }
        #pragma unroll
        for (int g = 0; g < 4; g++) {
            int col = half * 32 + g * 8;
            float4 f0 = make_float4(0.f, 0.f, 0.f, 0.f);
            float4 f1 = make_float4(0.f, 0.f, 0.f, 0.f);
            if (grow < M) {
                const float* p = Asrc + (size_t)grow * KA + kcc + col;
                f0 = *(const float4*)p;
                f1 = *(const float4*)(p + 4);
            }
            uint4 uh, ul;
            cvt8(f0, f1, uh, ul);
            uint32_t sw = SWZ((uint32_t)(lrow * 128 + col * 2));
            *(uint4*)(smem + OFF_AH + sw) = uh;
            *(uint4*)(smem + OFF_AL + sw) = ul;
        }
        // ---- stage + split B chunk [128 x 64] (rows bn..bn+128 of B) ----
        {
            const float* p0 = Bm + (size_t)(bn + lrow) * K + kc;
            #pragma unroll
            for (int g = 0; g < 4; g++) {
                int col = half * 32 + g * 8;
                float4 f0 = *(const float4*)(p0 + col);
                float4 f1 = *(const float4*)(p0 + col + 4);
                uint4 uh, ul;
                cvt8(f0, f1, uh, ul);
                uint32_t sw = SWZ((uint32_t)(lrow * 128 + col * 2));
                *(uint4*)(smem + OFF_BH + sw) = uh;
                *(uint4*)(smem + OFF_BL + sw) = ul;
            }
        }
        __syncthreads();

        // ---- compute: 4 k16-steps ----
        #pragma unroll
        for (int kk = 0; kk < 64; kk += 16) {
            // A fragments (2 m16 groups, hi+lo)
            uint32_t ah[2][4], al[2][4];
            #pragma unroll
            for (int mg = 0; mg < 2; mg++) {
                int row = wm * 32 + mg * 16 + (lane & 15);
                int bc  = kk * 2 + ((lane >> 4) << 4);
                uint32_t sw = SWZ((uint32_t)(row * 128 + bc));
                ldsm4(ah[mg], sb + OFF_AH + sw);
                ldsm4(al[mg], sb + OFF_AL + sw);
            }
            // B fragments (4 n16 pairs, hi+lo)
            uint32_t bh[4][4], bl[4][4];
            #pragma unroll
            for (int np = 0; np < 4; np++) {
                int nrow = wn * 64 + np * 16 + ((lane >> 4) << 3) + (lane & 7);
                int bc   = kk * 2 + (((lane >> 3) & 1) << 4);
                uint32_t sw = SWZ((uint32_t)(nrow * 128 + bc));
                ldsm4(bh[np], sb + OFF_BH + sw);
                ldsm4(bl[np], sb + OFF_BL + sw);
            }
            #pragma unroll
            for (int mg = 0; mg < 2; mg++)
                #pragma unroll
                for (int nt = 0; nt < 8; nt++) {
                    int np = nt >> 1, hb = (nt & 1) * 2;
                    mma_bf16(acc[mg][nt], ah[mg], bh[np][hb], bh[np][hb + 1]);
                    mma_bf16(acc[mg][nt], ah[mg], bl[np][hb], bl[np][hb + 1]);
                    mma_bf16(acc[mg][nt], al[mg], bh[np][hb], bh[np][hb + 1]);
                }
        }
        __syncthreads();
    }

    // ---- epilogue ----
    #pragma unroll
    for (int mg = 0; mg < 2; mg++) {
        int r0 = bm + wm * 32 + mg * 16 + (lane >> 2);
        #pragma unroll
        for (int rr = 0; rr < 2; rr++) {
            int row = r0 + rr * 8;
            if (row >= M) continue;
            float dg = DEG ? (float)g_deg[row] : 0.f;
            #pragma unroll
            for (int nt = 0; nt < 8; nt++) {
                int col = bn + wn * 64 + nt * 8 + (lane & 3) * 2;
                float v0 = acc[mg][nt][rr * 2]     + bias[col];
                float v1 = acc[mg][nt][rr * 2 + 1] + bias[col + 1];
                if (DEG) { v0 += dg * g_v[col]; v1 += dg * g_v[col + 1]; }
                if (ACT == 1) { v0 = fmaxf(v0, 0.f); v1 = fmaxf(v1, 0.f); }
                if (ACT == 2) { v0 = tanhf(v0); v1 = tanhf(v1); }
                *(float2*)(C + (size_t)row * NOUT + col) = make_float2(v0, v1);
            }
        }
    }
}

// ---------------- launch ----------------
extern "C" void kernel_launch(void* const* d_in, const int* in_sizes, int n_in,
                              void* d_out, int out_size) {
    (void)in_sizes; (void)n_in; (void)out_size;
    const float* x      = (const float*)d_in[0];
    const int*   ei     = (const int*)d_in[1];
    const float* enc_w1 = (const float*)d_in[3];
    const float* enc_b1 = (const float*)d_in[4];
    const float* enc_w2 = (const float*)d_in[5];
    const float* enc_b2 = (const float*)d_in[6];
    const float* msg_w  = (const float*)d_in[7];
    const float* msg_b  = (const float*)d_in[8];
    const float* dec_w1 = (const float*)d_in[9];
    const float* dec_b1 = (const float*)d_in[10];
    const float* dec_w2 = (const float*)d_in[11];
    const float* dec_b2 = (const float*)d_in[12];
    float* out = (float*)d_out;

    const int SM = 65536;
    cudaFuncSetAttribute(mm_gemm<1, 0, 0, 1, 0, 256>, cudaFuncAttributeMaxDynamicSharedMemorySize, SM);
    cudaFuncSetAttribute(mm_gemm<1, 1, 0, 2, 0, 256>, cudaFuncAttributeMaxDynamicSharedMemorySize, SM);
    cudaFuncSetAttribute(mm_gemm<1, 2, 1, 1, 1, 256>, cudaFuncAttributeMaxDynamicSharedMemorySize, SM);
    cudaFuncSetAttribute(mm_gemm<2, 1, 0, 0, 0, 128>, cudaFuncAttributeMaxDynamicSharedMemorySize, SM);

    zero_kernel<<<(NN + 255) / 256, 256>>>();
    combine_kernel<<<HH, HH>>>(dec_w1, msg_w, msg_b);
    hist_kernel<<<(EE + 255) / 256, 256>>>(ei);
    scan1_kernel<<<NB, 256>>>();
    scan2_kernel<<<1, 256>>>();
    scan3_kernel<<<NB, 256>>>();
    scatter_kernel<<<(EE + 255) / 256, 256>>>(ei);

    const int MT = (NN + 127) / 128;   // 391 M-tiles
    dim3 gH(MT, 2);   // NOUT=256
    dim3 gD(MT, 1);   // NOUT=128

    // enc1: g_h1 = relu(x @ enc_w1^T + b1), K=128
    mm_gemm<1, 0, 0, 1, 0, 256><<<gH, 256, SM>>>(x, enc_w1, DD, enc_b1, nullptr, NN);
    // enc2: g_h = relu(g_h1 @ enc_w2^T + b2), K=256
    mm_gemm<1, 1, 0, 2, 0, 256><<<gH, 256, SM>>>(nullptr, enc_w2, HH, enc_b2, nullptr, NN);
    // agg = sum_{edges} h[src]
    aggregate_kernel<<<(NN * 32 + 255) / 256, 256>>>();
    // dec1: g_h1 = relu(agg @ Wc^T + h @ dec_w1b^T + deg*v + b1), K=512 dual-A
    mm_gemm<1, 2, 1, 1, 1, 256><<<gH, 256, SM>>>(nullptr, nullptr, 2 * HH, dec_b1, nullptr, NN);
    // dec2: out = tanh(g_h1 @ dec_w2^T + b2), K=256, NOUT=128
    mm_gemm<2, 1, 0, 0, 0, 128><<<gD, 256, SM>>>(nullptr, dec_w2, HH, dec_b2, out, NN);
}

// round 12
// speedup vs baseline: 1.9058x; 1.2953x over previous
#include <cuda_runtime.h>
#include <cuda_bf16.h>
#include <cstdint>
#include <math.h>

#define NN 50000
#define EE 400000
#define DD 128
#define HH 256
#define NB 196    // ceil(NN/256)
#define NP 50048  // NN padded to 128-row tiles

// ---------------- scratch (static device globals) ----------------
__device__ float g_h   [NN * HH];                 // enc2 output fp32 (aggregate input)
__device__ float g_Bcat[HH * 2 * HH];             // [Wc | dec_w1b]
__device__ float g_v   [HH];
__device__ int   g_deg [NN];
__device__ int   g_fill[NN];
__device__ int   g_rowptr[NN + 1];
__device__ int   g_esrc[EE];
__device__ int   g_bsum[NB];
// bf16 hi/lo split operands
__device__ __nv_bfloat16 g_xh[NP * DD], g_xl[NP * DD];     // x split
__device__ __nv_bfloat16 g_ah[NP * HH], g_al[NP * HH];     // h1 split, reused as d split
__device__ __nv_bfloat16 g_hh[NP * HH], g_hl[NP * HH];     // h split
__device__ __nv_bfloat16 g_gh[NP * HH], g_gl[NP * HH];     // agg split
__device__ __nv_bfloat16 g_w1h[HH * DD],     g_w1l[HH * DD];      // enc_w1
__device__ __nv_bfloat16 g_w2h[HH * HH],     g_w2l[HH * HH];      // enc_w2
__device__ __nv_bfloat16 g_bch[HH * 2 * HH], g_bcl[HH * 2 * HH];  // Bcat
__device__ __nv_bfloat16 g_w3h[DD * HH],     g_w3l[DD * HH];      // dec_w2

// ---------------- helpers ----------------
__device__ __forceinline__ uint32_t smem_u32(const void* p) {
    uint32_t a;
    asm("{ .reg .u64 t; cvta.to.shared.u64 t, %1; cvt.u32.u64 %0, t; }" : "=r"(a) : "l"(p));
    return a;
}
#define SWZ(off) ((off) ^ (((off) >> 3) & 0x70))

__device__ __forceinline__ void ldsm4(uint32_t* r, uint32_t addr) {
    asm volatile("ldmatrix.sync.aligned.m8n8.x4.shared.b16 {%0,%1,%2,%3}, [%4];"
                 : "=r"(r[0]), "=r"(r[1]), "=r"(r[2]), "=r"(r[3]) : "r"(addr));
}
__device__ __forceinline__ void mma_bf16(float* c, const uint32_t* a,
                                         uint32_t b0, uint32_t b1) {
    asm volatile(
        "mma.sync.aligned.m16n8k16.row.col.f32.bf16.bf16.f32 "
        "{%0,%1,%2,%3}, {%4,%5,%6,%7}, {%8,%9}, {%0,%1,%2,%3};"
        : "+f"(c[0]), "+f"(c[1]), "+f"(c[2]), "+f"(c[3])
        : "r"(a[0]), "r"(a[1]), "r"(a[2]), "r"(a[3]), "r"(b0), "r"(b1));
}
__device__ __forceinline__ void cpa16(uint32_t d, const void* s) {
    asm volatile("cp.async.cg.shared.global [%0], [%1], 16;" :: "r"(d), "l"(s) : "memory");
}
#define CP_COMMIT() asm volatile("cp.async.commit_group;" ::: "memory")

__device__ __forceinline__ uint32_t pk2h(__nv_bfloat16 a, __nv_bfloat16 b) {
    uint16_t ua = *reinterpret_cast<uint16_t*>(&a);
    uint16_t ub = *reinterpret_cast<uint16_t*>(&b);
    return (uint32_t)ua | ((uint32_t)ub << 16);
}
// split float pair -> hi word + lo word
__device__ __forceinline__ void split2(float v0, float v1, uint32_t& hw, uint32_t& lw) {
    __nv_bfloat16 h0 = __float2bfloat16_rn(v0);
    __nv_bfloat16 h1 = __float2bfloat16_rn(v1);
    __nv_bfloat16 l0 = __float2bfloat16_rn(v0 - __bfloat162float(h0));
    __nv_bfloat16 l1 = __float2bfloat16_rn(v1 - __bfloat162float(h1));
    hw = pk2h(h0, h1);
    lw = pk2h(l0, l1);
}

// ---------------- init ----------------
__global__ void zero_kernel() {
    int i = blockIdx.x * blockDim.x + threadIdx.x;
    if (i < NN) { g_deg[i] = 0; g_fill[i] = 0; }
}

// ---------------- generic fp32 -> bf16 hi/lo split ----------------
// DSEL: 0=x, 1=w1, 2=w2, 3=w3, 4=bcat(src=g_Bcat)
template<int DSEL>
__global__ void split_kernel(const float* __restrict__ src, int n_src, int n_tot) {
    int i = blockIdx.x * blockDim.x + threadIdx.x;
    if (i * 2 >= n_tot) return;
    const float* s = (DSEL == 4) ? g_Bcat : src;
    float v0 = (i * 2     < n_src) ? s[i * 2]     : 0.f;
    float v1 = (i * 2 + 1 < n_src) ? s[i * 2 + 1] : 0.f;
    uint32_t hw, lw;
    split2(v0, v1, hw, lw);
    __nv_bfloat16 *dh, *dl;
    if (DSEL == 0)      { dh = g_xh;  dl = g_xl;  }
    else if (DSEL == 1) { dh = g_w1h; dl = g_w1l; }
    else if (DSEL == 2) { dh = g_w2h; dl = g_w2l; }
    else if (DSEL == 3) { dh = g_w3h; dl = g_w3l; }
    else                { dh = g_bch; dl = g_bcl; }
    *(uint32_t*)&dh[i * 2] = hw;
    *(uint32_t*)&dl[i * 2] = lw;
}

// ---------------- fold msg GEMM into decoder weights ----------------
__global__ void combine_kernel(const float* __restrict__ dec_w1,
                               const float* __restrict__ msg_w,
                               const float* __restrict__ msg_b) {
    int i = blockIdx.x;
    int k = threadIdx.x;
    __shared__ float srow[HH];
    srow[k] = dec_w1[i * 2 * HH + k];
    __syncthreads();
    float sum = 0.f;
    #pragma unroll 8
    for (int j = 0; j < HH; j++)
        sum = fmaf(srow[j], msg_w[j * HH + k], sum);
    g_Bcat[i * 2 * HH + k]      = sum;
    g_Bcat[i * 2 * HH + HH + k] = dec_w1[i * 2 * HH + HH + k];

    __shared__ float red[HH];
    red[k] = srow[k] * msg_b[k];
    __syncthreads();
    for (int off = HH / 2; off > 0; off >>= 1) {
        if (k < off) red[k] += red[k + off];
        __syncthreads();
    }
    if (k == 0) g_v[i] = red[0];
}

// ---------------- CSR build ----------------
__global__ void hist_kernel(const int* __restrict__ ei) {
    int e = blockIdx.x * blockDim.x + threadIdx.x;
    if (e < EE) {
        int dd = ei[EE + e];
        if (dd >= 0 && dd < NN) atomicAdd(&g_deg[dd], 1);
    }
}
__global__ void scan1_kernel() {
    __shared__ int sm[256];
    int t = threadIdx.x;
    int idx = blockIdx.x * 256 + t;
    sm[t] = (idx < NN) ? g_deg[idx] : 0;
    __syncthreads();
    for (int off = 128; off > 0; off >>= 1) {
        if (t < off) sm[t] += sm[t + off];
        __syncthreads();
    }
    if (t == 0) g_bsum[blockIdx.x] = sm[0];
}
__global__ void scan2_kernel() {
    int t = threadIdx.x;
    int v = (t < NB) ? g_bsum[t] : 0;
    __shared__ int sm[256];
    sm[t] = v;
    __syncthreads();
    for (int off = 1; off < 256; off <<= 1) {
        int u = (t >= off) ? sm[t - off] : 0;
        __syncthreads();
        sm[t] += u;
        __syncthreads();
    }
    if (t < NB) g_bsum[t] = sm[t] - v;
}
__global__ void scan3_kernel() {
    __shared__ int sm[256];
    int t = threadIdx.x;
    int idx = blockIdx.x * 256 + t;
    int v = (idx < NN) ? g_deg[idx] : 0;
    sm[t] = v;
    __syncthreads();
    for (int off = 1; off < 256; off <<= 1) {
        int u = (t >= off) ? sm[t - off] : 0;
        __syncthreads();
        sm[t] += u;
        __syncthreads();
    }
    if (idx <= NN) g_rowptr[idx] = g_bsum[blockIdx.x] + sm[t] - v;
}
__global__ void scatter_kernel(const int* __restrict__ ei) {
    int e = blockIdx.x * blockDim.x + threadIdx.x;
    if (e < EE) {
        int dd = ei[EE + e];
        if (dd >= 0 && dd < NN) {
            int pos = g_rowptr[dd] + atomicAdd(&g_fill[dd], 1);
            g_esrc[pos] = ei[e];
        }
    }
}

// ---------------- aggregation: warp per node; writes bf16 hi/lo split ---------------
__global__ void aggregate_kernel() {
    int warp = (blockIdx.x * blockDim.x + threadIdx.x) >> 5;
    int lane = threadIdx.x & 31;
    if (warp >= NN) return;
    int s0 = g_rowptr[warp], s1 = g_rowptr[warp + 1];
    float4 acc0 = make_float4(0.f, 0.f, 0.f, 0.f);
    float4 acc1 = make_float4(0.f, 0.f, 0.f, 0.f);
    for (int e = s0; e < s1; e++) {
        const float4* r = (const float4*)(g_h + (size_t)g_esrc[e] * HH);
        float4 x0 = __ldg(&r[lane]);
        float4 x1 = __ldg(&r[lane + 32]);
        acc0.x += x0.x; acc0.y += x0.y; acc0.z += x0.z; acc0.w += x0.w;
        acc1.x += x1.x; acc1.y += x1.y; acc1.z += x1.z; acc1.w += x1.w;
    }
    size_t base = (size_t)warp * HH + lane * 4;
    uint32_t hw, lw;
    split2(acc0.x, acc0.y, hw, lw);
    *(uint32_t*)&g_gh[base] = hw;     *(uint32_t*)&g_gl[base] = lw;
    split2(acc0.z, acc0.w, hw, lw);
    *(uint32_t*)&g_gh[base + 2] = hw; *(uint32_t*)&g_gl[base + 2] = lw;
    split2(acc1.x, acc1.y, hw, lw);
    *(uint32_t*)&g_gh[base + 128] = hw;     *(uint32_t*)&g_gl[base + 128] = lw;
    split2(acc1.z, acc1.w, hw, lw);
    *(uint32_t*)&g_gh[base + 130] = hw;     *(uint32_t*)&g_gl[base + 130] = lw;
}

// ========== bf16-split tensor GEMM, pre-split operands, cp.async double-buffer ======
// C = act(A @ B^T + bias [+ deg*v]);  3-term: Ah.Bh + Ah.Bl + Al.Bh, fp32 accum.
// Block 128x128, 8 warps (warp tile 32x64). K-chunks of 64, 2-stage cp.async pipeline.
// ASEL: 0 = x-split (KA=128), 1 = a-split (KA=256), 2 = dual [g-split | h-split]
// BSEL: 0 = w1, 1 = w2, 2 = bcat, 3 = w3
// CSEL: 0 = a-split (h1 or d), 1 = g_h fp32 + h-split, 2 = Cparam fp32
template<int ACT, int ASEL, int BSEL, int CSEL, int DEG, int NOUT>
__global__ void __launch_bounds__(256, 1)
mm_gemm(int K, const float* __restrict__ bias, float* __restrict__ Cparam, int M)
{
    constexpr int STAGE_BYTES = 65536;
    constexpr int OFF_AH = 0, OFF_AL = 16384, OFF_BH = 32768, OFF_BL = 49152;
    constexpr int KA = (ASEL == 0) ? DD : HH;

    extern __shared__ char smem[];
    const uint32_t sb = smem_u32(smem);
    const int tid  = threadIdx.x;
    const int wid  = tid >> 5;
    const int lane = tid & 31;
    const int wm   = wid & 3;
    const int wn   = wid >> 2;

    const __nv_bfloat16* Bh_;
    const __nv_bfloat16* Bl_;
    if (BSEL == 0)      { Bh_ = g_w1h; Bl_ = g_w1l; }
    else if (BSEL == 1) { Bh_ = g_w2h; Bl_ = g_w2l; }
    else if (BSEL == 2) { Bh_ = g_bch; Bl_ = g_bcl; }
    else                { Bh_ = g_w3h; Bl_ = g_w3l; }

    const int bm = blockIdx.x * 128;
    const int bn = blockIdx.y * 128;
    const int NC = K / 64;

    const int srow = tid >> 1;          // 0..127
    const int sus  = (tid & 1) * 4;     // unit start 0 or 4

    // ---- stage issue lambda (chunk c -> buffer c&1) ----
    auto issue = [&](int c) {
        int kc = c * 64;
        uint32_t base = sb + (uint32_t)(c & 1) * STAGE_BYTES;
        const __nv_bfloat16 *Ah_, *Al_;
        int kcc = kc;
        if (ASEL == 0)      { Ah_ = g_xh; Al_ = g_xl; }
        else if (ASEL == 1) { Ah_ = g_ah; Al_ = g_al; }
        else {
            if (kc < HH) { Ah_ = g_gh; Al_ = g_gl; }
            else         { Ah_ = g_hh; Al_ = g_hl; kcc = kc - HH; }
        }
        const size_t arow = (size_t)(bm + srow) * KA + kcc;
        const size_t brow = (size_t)(bn + srow) * K + kc;
        #pragma unroll
        for (int u = 0; u < 4; u++) {
            int unit = sus + u;
            uint32_t sw = SWZ((uint32_t)(srow * 128 + unit * 16));
            cpa16(base + OFF_AH + sw, Ah_ + arow + unit * 8);
            cpa16(base + OFF_AL + sw, Al_ + arow + unit * 8);
            cpa16(base + OFF_BH + sw, Bh_ + brow + unit * 8);
            cpa16(base + OFF_BL + sw, Bl_ + brow + unit * 8);
        }
        CP_COMMIT();
    };

    float acc[2][8][4];
    #pragma unroll
    for (int mg = 0; mg < 2; mg++)
        #pragma unroll
        for (int nt = 0; nt < 8; nt++)
            #pragma unroll
            for (int q = 0; q < 4; q++) acc[mg][nt][q] = 0.f;

    issue(0);
    for (int c = 0; c < NC; c++) {
        if (c + 1 < NC) {
            issue(c + 1);
            asm volatile("cp.async.wait_group 1;" ::: "memory");
        } else {
            asm volatile("cp.async.wait_group 0;" ::: "memory");
        }
        __syncthreads();

        uint32_t base = sb + (uint32_t)(c & 1) * STAGE_BYTES;
        #pragma unroll
        for (int kk = 0; kk < 64; kk += 16) {
            uint32_t ah[2][4], al[2][4];
            #pragma unroll
            for (int mg = 0; mg < 2; mg++) {
                int row = wm * 32 + mg * 16 + (lane & 15);
                int bc  = kk * 2 + ((lane >> 4) << 4);
                uint32_t sw = SWZ((uint32_t)(row * 128 + bc));
                ldsm4(ah[mg], base + OFF_AH + sw);
                ldsm4(al[mg], base + OFF_AL + sw);
            }
            uint32_t bh[4][4], bl[4][4];
            #pragma unroll
            for (int np = 0; np < 4; np++) {
                int nrow = wn * 64 + np * 16 + ((lane >> 4) << 3) + (lane & 7);
                int bc   = kk * 2 + (((lane >> 3) & 1) << 4);
                uint32_t sw = SWZ((uint32_t)(nrow * 128 + bc));
                ldsm4(bh[np], base + OFF_BH + sw);
                ldsm4(bl[np], base + OFF_BL + sw);
            }
            #pragma unroll
            for (int mg = 0; mg < 2; mg++)
                #pragma unroll
                for (int nt = 0; nt < 8; nt++) {
                    int np = nt >> 1, hb = (nt & 1) * 2;
                    mma_bf16(acc[mg][nt], ah[mg], bh[np][hb], bh[np][hb + 1]);
                    mma_bf16(acc[mg][nt], ah[mg], bl[np][hb], bl[np][hb + 1]);
                    mma_bf16(acc[mg][nt], al[mg], bh[np][hb], bh[np][hb + 1]);
                }
        }
        __syncthreads();
    }

    // ---- epilogue ----
    #pragma unroll
    for (int mg = 0; mg < 2; mg++) {
        int r0 = bm + wm * 32 + mg * 16 + (lane >> 2);
        #pragma unroll
        for (int rr = 0; rr < 2; rr++) {
            int row = r0 + rr * 8;
            if (row >= M) continue;
            float dg = DEG ? (float)g_deg[row] : 0.f;
            #pragma unroll
            for (int nt = 0; nt < 8; nt++) {
                int col = bn + wn * 64 + nt * 8 + (lane & 3) * 2;
                float v0 = acc[mg][nt][rr * 2]     + bias[col];
                float v1 = acc[mg][nt][rr * 2 + 1] + bias[col + 1];
                if (DEG) { v0 += dg * g_v[col]; v1 += dg * g_v[col + 1]; }
                if (ACT == 1) { v0 = fmaxf(v0, 0.f); v1 = fmaxf(v1, 0.f); }
                if (ACT == 2) { v0 = tanhf(v0); v1 = tanhf(v1); }
                size_t off = (size_t)row * NOUT + col;
                if (CSEL == 0) {
                    uint32_t hw, lw;
                    split2(v0, v1, hw, lw);
                    *(uint32_t*)&g_ah[off] = hw;
                    *(uint32_t*)&g_al[off] = lw;
                } else if (CSEL == 1) {
                    *(float2*)(g_h + off) = make_float2(v0, v1);
                    uint32_t hw, lw;
                    split2(v0, v1, hw, lw);
                    *(uint32_t*)&g_hh[off] = hw;
                    *(uint32_t*)&g_hl[off] = lw;
                } else {
                    *(float2*)(Cparam + off) = make_float2(v0, v1);
                }
            }
        }
    }
}

// ---------------- launch ----------------
extern "C" void kernel_launch(void* const* d_in, const int* in_sizes, int n_in,
                              void* d_out, int out_size) {
    (void)in_sizes; (void)n_in; (void)out_size;
    const float* x      = (const float*)d_in[0];
    const int*   ei     = (const int*)d_in[1];
    const float* enc_w1 = (const float*)d_in[3];
    const float* enc_b1 = (const float*)d_in[4];
    const float* enc_w2 = (const float*)d_in[5];
    const float* enc_b2 = (const float*)d_in[6];
    const float* msg_w  = (const float*)d_in[7];
    const float* msg_b  = (const float*)d_in[8];
    const float* dec_w1 = (const float*)d_in[9];
    const float* dec_b1 = (const float*)d_in[10];
    const float* dec_w2 = (const float*)d_in[11];
    const float* dec_b2 = (const float*)d_in[12];
    float* out = (float*)d_out;

    const int SM = 131072;
    cudaFuncSetAttribute(mm_gemm<1, 0, 0, 0, 0, 256>, cudaFuncAttributeMaxDynamicSharedMemorySize, SM);
    cudaFuncSetAttribute(mm_gemm<1, 1, 1, 1, 0, 256>, cudaFuncAttributeMaxDynamicSharedMemorySize, SM);
    cudaFuncSetAttribute(mm_gemm<1, 2, 2, 0, 1, 256>, cudaFuncAttributeMaxDynamicSharedMemorySize, SM);
    cudaFuncSetAttribute(mm_gemm<2, 1, 3, 2, 0, 128>, cudaFuncAttributeMaxDynamicSharedMemorySize, SM);

    zero_kernel<<<(NN + 255) / 256, 256>>>();
    combine_kernel<<<HH, HH>>>(dec_w1, msg_w, msg_b);
    // one-shot splits (pairs per thread)
    split_kernel<0><<<(NP * DD / 2 + 255) / 256, 256>>>(x, NN * DD, NP * DD);
    split_kernel<1><<<(HH * DD / 2 + 255) / 256, 256>>>(enc_w1, HH * DD, HH * DD);
    split_kernel<2><<<(HH * HH / 2 + 255) / 256, 256>>>(enc_w2, HH * HH, HH * HH);
    split_kernel<3><<<(DD * HH / 2 + 255) / 256, 256>>>(dec_w2, DD * HH, DD * HH);
    split_kernel<4><<<(HH * 2 * HH / 2 + 255) / 256, 256>>>(nullptr, HH * 2 * HH, HH * 2 * HH);
    hist_kernel<<<(EE + 255) / 256, 256>>>(ei);
    scan1_kernel<<<NB, 256>>>();
    scan2_kernel<<<1, 256>>>();
    scan3_kernel<<<NB, 256>>>();
    scatter_kernel<<<(EE + 255) / 256, 256>>>(ei);

    const int MT = (NN + 127) / 128;   // 391 M-tiles
    dim3 gH(MT, 2);   // NOUT=256
    dim3 gD(MT, 1);   // NOUT=128

    // enc1: h1-split = relu(x @ enc_w1^T + b1), K=128
    mm_gemm<1, 0, 0, 0, 0, 256><<<gH, 256, SM>>>(DD, enc_b1, nullptr, NN);
    // enc2: g_h fp32 + h-split = relu(h1 @ enc_w2^T + b2), K=256
    mm_gemm<1, 1, 1, 1, 0, 256><<<gH, 256, SM>>>(HH, enc_b2, nullptr, NN);
    // agg-split = sum_{edges} h[src]
    aggregate_kernel<<<(NN * 32 + 255) / 256, 256>>>();
    // dec1: d-split = relu(agg @ Wc^T + h @ dec_w1b^T + deg*v + b1), K=512 dual-A
    mm_gemm<1, 2, 2, 0, 1, 256><<<gH, 256, SM>>>(2 * HH, dec_b1, nullptr, NN);
    // dec2: out = tanh(d @ dec_w2^T + b2), K=256, NOUT=128
    mm_gemm<2, 1, 3, 2, 0, 128><<<gD, 256, SM>>>(HH, dec_b2, out, NN);
}

// round 13
// speedup vs baseline: 2.3657x; 1.2413x over previous
#include <cuda_runtime.h>
#include <cuda_bf16.h>
#include <cstdint>
#include <math.h>

#define NN 50000
#define EE 400000
#define DD 128
#define HH 256
#define NB 196    // ceil(NN/256)
#define NP 50048  // NN padded to 128-row tiles

// ---------------- scratch (static device globals) ----------------
__device__ float g_h   [NN * HH];                 // enc2 output fp32 (aggregate input)
__device__ float g_v   [HH];
__device__ int   g_deg [NN];
__device__ int   g_fill[NN];
__device__ int   g_rowptr[NN + 1];
__device__ int   g_esrc[EE];
__device__ int   g_bsum[NB];
// bf16 hi/lo split operands
__device__ __nv_bfloat16 g_xh[NP * DD], g_xl[NP * DD];     // x split
__device__ __nv_bfloat16 g_ah[NP * HH], g_al[NP * HH];     // h1 split, reused as d split
__device__ __nv_bfloat16 g_hh[NP * HH], g_hl[NP * HH];     // h split
__device__ __nv_bfloat16 g_gh[NP * HH], g_gl[NP * HH];     // agg split
__device__ __nv_bfloat16 g_w1h[HH * DD],     g_w1l[HH * DD];      // enc_w1
__device__ __nv_bfloat16 g_w2h[HH * HH],     g_w2l[HH * HH];      // enc_w2
__device__ __nv_bfloat16 g_bch[HH * 2 * HH], g_bcl[HH * 2 * HH];  // [Wc | dec_w1b]
__device__ __nv_bfloat16 g_w3h[DD * HH],     g_w3l[DD * HH];      // dec_w2

// ---------------- helpers ----------------
__device__ __forceinline__ uint32_t smem_u32(const void* p) {
    uint32_t a;
    asm("{ .reg .u64 t; cvta.to.shared.u64 t, %1; cvt.u32.u64 %0, t; }" : "=r"(a) : "l"(p));
    return a;
}
#define SWZ(off) ((off) ^ (((off) >> 3) & 0x70))

__device__ __forceinline__ void ldsm4(uint32_t* r, uint32_t addr) {
    asm volatile("ldmatrix.sync.aligned.m8n8.x4.shared.b16 {%0,%1,%2,%3}, [%4];"
                 : "=r"(r[0]), "=r"(r[1]), "=r"(r[2]), "=r"(r[3]) : "r"(addr));
}
__device__ __forceinline__ void mma_bf16(float* c, const uint32_t* a,
                                         uint32_t b0, uint32_t b1) {
    asm volatile(
        "mma.sync.aligned.m16n8k16.row.col.f32.bf16.bf16.f32 "
        "{%0,%1,%2,%3}, {%4,%5,%6,%7}, {%8,%9}, {%0,%1,%2,%3};"
        : "+f"(c[0]), "+f"(c[1]), "+f"(c[2]), "+f"(c[3])
        : "r"(a[0]), "r"(a[1]), "r"(a[2]), "r"(a[3]), "r"(b0), "r"(b1));
}
__device__ __forceinline__ void cpa16(uint32_t d, const void* s) {
    asm volatile("cp.async.cg.shared.global [%0], [%1], 16;" :: "r"(d), "l"(s) : "memory");
}
#define CP_COMMIT() asm volatile("cp.async.commit_group;" ::: "memory")

__device__ __forceinline__ uint32_t pk2h(__nv_bfloat16 a, __nv_bfloat16 b) {
    uint16_t ua = *reinterpret_cast<uint16_t*>(&a);
    uint16_t ub = *reinterpret_cast<uint16_t*>(&b);
    return (uint32_t)ua | ((uint32_t)ub << 16);
}
__device__ __forceinline__ void split2(float v0, float v1, uint32_t& hw, uint32_t& lw) {
    __nv_bfloat16 h0 = __float2bfloat16_rn(v0);
    __nv_bfloat16 h1 = __float2bfloat16_rn(v1);
    __nv_bfloat16 l0 = __float2bfloat16_rn(v0 - __bfloat162float(h0));
    __nv_bfloat16 l1 = __float2bfloat16_rn(v1 - __bfloat162float(h1));
    hw = pk2h(h0, h1);
    lw = pk2h(l0, l1);
}

// ---------------- fused one-shot splits + counter zeroing (single launch) -----------
// block ranges: [0,BX) x | [BX,BX+64) w1 | [..,+128) w2 | [..,+64) w3 | [..,+196) zero
#define BX (NP * DD / 2 / 256)   // 12512
__global__ void split_all_kernel(const float* __restrict__ x,
                                 const float* __restrict__ w1,
                                 const float* __restrict__ w2,
                                 const float* __restrict__ w3) {
    int b = blockIdx.x;
    if (b < BX) {
        int i = b * 256 + threadIdx.x;           // pair index
        float v0 = 0.f, v1 = 0.f;
        if (i * 2 + 1 < NN * DD) { v0 = x[i * 2]; v1 = x[i * 2 + 1]; }
        else if (i * 2 < NN * DD) { v0 = x[i * 2]; }
        uint32_t hw, lw;
        split2(v0, v1, hw, lw);
        *(uint32_t*)&g_xh[i * 2] = hw;
        *(uint32_t*)&g_xl[i * 2] = lw;
        return;
    }
    b -= BX;
    if (b < 64) {            // w1: HH*DD = 32768 elems, 16384 pairs
        int i = b * 256 + threadIdx.x;
        uint32_t hw, lw;
        split2(w1[i * 2], w1[i * 2 + 1], hw, lw);
        *(uint32_t*)&g_w1h[i * 2] = hw;
        *(uint32_t*)&g_w1l[i * 2] = lw;
        return;
    }
    b -= 64;
    if (b < 128) {           // w2: HH*HH = 65536 elems
        int i = b * 256 + threadIdx.x;
        uint32_t hw, lw;
        split2(w2[i * 2], w2[i * 2 + 1], hw, lw);
        *(uint32_t*)&g_w2h[i * 2] = hw;
        *(uint32_t*)&g_w2l[i * 2] = lw;
        return;
    }
    b -= 128;
    if (b < 64) {            // w3: DD*HH = 32768 elems
        int i = b * 256 + threadIdx.x;
        uint32_t hw, lw;
        split2(w3[i * 2], w3[i * 2 + 1], hw, lw);
        *(uint32_t*)&g_w3h[i * 2] = hw;
        *(uint32_t*)&g_w3l[i * 2] = lw;
        return;
    }
    b -= 64;
    {                        // zero deg/fill
        int i = b * 256 + threadIdx.x;
        if (i < NN) { g_deg[i] = 0; g_fill[i] = 0; }
    }
}

// ---------------- combine: fold msg GEMM; writes bf16 split of [Wc | w1b] + g_v -----
__global__ void combine_kernel(const float* __restrict__ dec_w1,
                               const float* __restrict__ msg_w,
                               const float* __restrict__ msg_b) {
    int i = blockIdx.x;     // 0..255 (output row)
    int k = threadIdx.x;    // 0..255
    __shared__ float srow[HH];
    __shared__ float wcs[HH];
    srow[k] = dec_w1[i * 2 * HH + k];
    __syncthreads();
    float sum = 0.f;
    #pragma unroll 8
    for (int j = 0; j < HH; j++)
        sum = fmaf(srow[j], msg_w[j * HH + k], sum);
    wcs[k] = sum;

    __shared__ float red[HH];
    red[k] = srow[k] * msg_b[k];
    __syncthreads();

    // write pairs: threads 0-127 -> Wc part, 128-255 -> dec_w1b part
    uint32_t hw, lw;
    if (k < 128) {
        split2(wcs[2 * k], wcs[2 * k + 1], hw, lw);
        *(uint32_t*)&g_bch[i * 2 * HH + 2 * k] = hw;
        *(uint32_t*)&g_bcl[i * 2 * HH + 2 * k] = lw;
    } else {
        int j = 2 * (k - 128);
        split2(dec_w1[i * 2 * HH + HH + j], dec_w1[i * 2 * HH + HH + j + 1], hw, lw);
        *(uint32_t*)&g_bch[i * 2 * HH + HH + j] = hw;
        *(uint32_t*)&g_bcl[i * 2 * HH + HH + j] = lw;
    }

    for (int off = HH / 2; off > 0; off >>= 1) {
        if (k < off) red[k] += red[k + off];
        __syncthreads();
    }
    if (k == 0) g_v[i] = red[0];
}

// ---------------- CSR build ----------------
__global__ void hist_kernel(const int* __restrict__ ei) {
    int e = blockIdx.x * blockDim.x + threadIdx.x;
    if (e < EE) {
        int dd = ei[EE + e];
        if (dd >= 0 && dd < NN) atomicAdd(&g_deg[dd], 1);
    }
}
__global__ void scan1_kernel() {
    __shared__ int sm[256];
    int t = threadIdx.x;
    int idx = blockIdx.x * 256 + t;
    sm[t] = (idx < NN) ? g_deg[idx] : 0;
    __syncthreads();
    for (int off = 128; off > 0; off >>= 1) {
        if (t < off) sm[t] += sm[t + off];
        __syncthreads();
    }
    if (t == 0) g_bsum[blockIdx.x] = sm[0];
}
__global__ void scan2_kernel() {
    int t = threadIdx.x;
    int v = (t < NB) ? g_bsum[t] : 0;
    __shared__ int sm[256];
    sm[t] = v;
    __syncthreads();
    for (int off = 1; off < 256; off <<= 1) {
        int u = (t >= off) ? sm[t - off] : 0;
        __syncthreads();
        sm[t] += u;
        __syncthreads();
    }
    if (t < NB) g_bsum[t] = sm[t] - v;
}
__global__ void scan3_kernel() {
    __shared__ int sm[256];
    int t = threadIdx.x;
    int idx = blockIdx.x * 256 + t;
    int v = (idx < NN) ? g_deg[idx] : 0;
    sm[t] = v;
    __syncthreads();
    for (int off = 1; off < 256; off <<= 1) {
        int u = (t >= off) ? sm[t - off] : 0;
        __syncthreads();
        sm[t] += u;
        __syncthreads();
    }
    if (idx <= NN) g_rowptr[idx] = g_bsum[blockIdx.x] + sm[t] - v;
}
__global__ void scatter_kernel(const int* __restrict__ ei) {
    int e = blockIdx.x * blockDim.x + threadIdx.x;
    if (e < EE) {
        int dd = ei[EE + e];
        if (dd >= 0 && dd < NN) {
            int pos = g_rowptr[dd] + atomicAdd(&g_fill[dd], 1);
            g_esrc[pos] = ei[e];
        }
    }
}

// ---------------- aggregation: warp per node; writes bf16 hi/lo split ---------------
__global__ void aggregate_kernel() {
    int warp = (blockIdx.x * blockDim.x + threadIdx.x) >> 5;
    int lane = threadIdx.x & 31;
    if (warp >= NN) return;
    int s0 = g_rowptr[warp], s1 = g_rowptr[warp + 1];
    float4 acc0 = make_float4(0.f, 0.f, 0.f, 0.f);
    float4 acc1 = make_float4(0.f, 0.f, 0.f, 0.f);
    for (int e = s0; e < s1; e++) {
        const float4* r = (const float4*)(g_h + (size_t)g_esrc[e] * HH);
        float4 x0 = __ldg(&r[lane]);
        float4 x1 = __ldg(&r[lane + 32]);
        acc0.x += x0.x; acc0.y += x0.y; acc0.z += x0.z; acc0.w += x0.w;
        acc1.x += x1.x; acc1.y += x1.y; acc1.z += x1.z; acc1.w += x1.w;
    }
    size_t base = (size_t)warp * HH + lane * 4;
    uint32_t hw, lw;
    split2(acc0.x, acc0.y, hw, lw);
    *(uint32_t*)&g_gh[base] = hw;     *(uint32_t*)&g_gl[base] = lw;
    split2(acc0.z, acc0.w, hw, lw);
    *(uint32_t*)&g_gh[base + 2] = hw; *(uint32_t*)&g_gl[base + 2] = lw;
    split2(acc1.x, acc1.y, hw, lw);
    *(uint32_t*)&g_gh[base + 128] = hw; *(uint32_t*)&g_gl[base + 128] = lw;
    split2(acc1.z, acc1.w, hw, lw);
    *(uint32_t*)&g_gh[base + 130] = hw; *(uint32_t*)&g_gl[base + 130] = lw;
}

// ========== bf16-split tensor GEMM, MG=4 warp tiles (64 x NT*8), full-N blocks ======
// Block: 128 rows x NOUT cols, 8 warps (wm = wid&1 -> 2 row groups of 64,
// wn = wid>>1 -> 4 col groups of NT*8).  K-chunks of 64, 2-stage cp.async pipeline.
// 3-term: Ah.Bh + Ah.Bl + Al.Bh, fp32 accum.
// ASEL: 0 = x-split (KA=128), 1 = a-split (KA=256), 2 = dual [g-split | h-split]
// BSEL: 0 = w1, 1 = w2, 2 = bcat, 3 = w3
// CSEL: 0 = a-split (h1 or d), 1 = g_h fp32 + h-split, 2 = Cparam fp32
template<int ACT, int ASEL, int BSEL, int CSEL, int DEG, int NOUT>
__global__ void __launch_bounds__(256, 1)
mm_gemm(int K, const float* __restrict__ bias, float* __restrict__ Cparam, int M)
{
    constexpr int NT = NOUT / 32;                  // n8 tiles per warp (8 or 4)
    constexpr int OFF_AH = 0, OFF_AL = 16384, OFF_BH = 32768;
    constexpr int OFF_BL = OFF_BH + NOUT * 128;
    constexpr int STAGE_BYTES = 32768 + 2 * NOUT * 128;
    constexpr int KA = (ASEL == 0) ? DD : HH;

    extern __shared__ char smem[];
    const uint32_t sb = smem_u32(smem);
    const int tid  = threadIdx.x;
    const int wid  = tid >> 5;
    const int lane = tid & 31;
    const int wm   = wid & 1;       // row group (64 rows)
    const int wn   = wid >> 1;      // col group (NT*8 cols)

    const __nv_bfloat16* Bh_;
    const __nv_bfloat16* Bl_;
    if (BSEL == 0)      { Bh_ = g_w1h; Bl_ = g_w1l; }
    else if (BSEL == 1) { Bh_ = g_w2h; Bl_ = g_w2l; }
    else if (BSEL == 2) { Bh_ = g_bch; Bl_ = g_bcl; }
    else                { Bh_ = g_w3h; Bl_ = g_w3l; }

    const int bm = blockIdx.x * 128;
    const int NC = K / 64;

    // ---- stage issue (chunk c -> buffer c&1) ----
    auto issue = [&](int c) {
        int kc = c * 64;
        uint32_t base = sb + (uint32_t)(c & 1) * STAGE_BYTES;
        const __nv_bfloat16 *Ah_, *Al_;
        int kcc = kc;
        if (ASEL == 0)      { Ah_ = g_xh; Al_ = g_xl; }
        else if (ASEL == 1) { Ah_ = g_ah; Al_ = g_al; }
        else {
            if (kc < HH) { Ah_ = g_gh; Al_ = g_gl; }
            else         { Ah_ = g_hh; Al_ = g_hl; kcc = kc - HH; }
        }
        #pragma unroll
        for (int i = tid; i < 1024; i += 256) {        // A: 128 rows x 8 units
            int row = i >> 3, unit = i & 7;
            uint32_t sw = SWZ((uint32_t)(row * 128 + unit * 16));
            size_t go = (size_t)(bm + row) * KA + kcc + unit * 8;
            cpa16(base + OFF_AH + sw, Ah_ + go);
            cpa16(base + OFF_AL + sw, Al_ + go);
        }
        #pragma unroll
        for (int i = tid; i < NOUT * 8; i += 256) {    // B: NOUT rows x 8 units
            int row = i >> 3, unit = i & 7;
            uint32_t sw = SWZ((uint32_t)(row * 128 + unit * 16));
            size_t go = (size_t)row * K + kc + unit * 8;
            cpa16(base + OFF_BH + sw, Bh_ + go);
            cpa16(base + OFF_BL + sw, Bl_ + go);
        }
        CP_COMMIT();
    };

    float acc[4][NT][4];
    #pragma unroll
    for (int mg = 0; mg < 4; mg++)
        #pragma unroll
        for (int nt = 0; nt < NT; nt++)
            #pragma unroll
            for (int q = 0; q < 4; q++) acc[mg][nt][q] = 0.f;

    issue(0);
    for (int c = 0; c < NC; c++) {
        if (c + 1 < NC) {
            issue(c + 1);
            asm volatile("cp.async.wait_group 1;" ::: "memory");
        } else {
            asm volatile("cp.async.wait_group 0;" ::: "memory");
        }
        __syncthreads();

        uint32_t base = sb + (uint32_t)(c & 1) * STAGE_BYTES;
        #pragma unroll
        for (int kk = 0; kk < 64; kk += 16) {
            uint32_t ah[4][4], al[4][4];
            #pragma unroll
            for (int mg = 0; mg < 4; mg++) {
                int row = wm * 64 + mg * 16 + (lane & 15);
                int bc  = kk * 2 + ((lane >> 4) << 4);
                uint32_t sw = SWZ((uint32_t)(row * 128 + bc));
                ldsm4(ah[mg], base + OFF_AH + sw);
                ldsm4(al[mg], base + OFF_AL + sw);
            }
            uint32_t bh[NT / 2][4], bl[NT / 2][4];
            #pragma unroll
            for (int np = 0; np < NT / 2; np++) {
                int nrow = wn * (NT * 8) + np * 16 + ((lane >> 4) << 3) + (lane & 7);
                int bc   = kk * 2 + (((lane >> 3) & 1) << 4);
                uint32_t sw = SWZ((uint32_t)(nrow * 128 + bc));
                ldsm4(bh[np], base + OFF_BH + sw);
                ldsm4(bl[np], base + OFF_BL + sw);
            }
            #pragma unroll
            for (int mg = 0; mg < 4; mg++)
                #pragma unroll
                for (int nt = 0; nt < NT; nt++) {
                    int np = nt >> 1, hb = (nt & 1) * 2;
                    mma_bf16(acc[mg][nt], ah[mg], bh[np][hb], bh[np][hb + 1]);
                    mma_bf16(acc[mg][nt], ah[mg], bl[np][hb], bl[np][hb + 1]);
                    mma_bf16(acc[mg][nt], al[mg], bh[np][hb], bh[np][hb + 1]);
                }
        }
        __syncthreads();
    }

    // ---- epilogue ----
    #pragma unroll
    for (int mg = 0; mg < 4; mg++) {
        int r0 = bm + wm * 64 + mg * 16 + (lane >> 2);
        #pragma unroll
        for (int rr = 0; rr < 2; rr++) {
            int row = r0 + rr * 8;
            if (row >= M) continue;
            float dg = DEG ? (float)g_deg[row] : 0.f;
            #pragma unroll
            for (int nt = 0; nt < NT; nt++) {
                int col = wn * (NT * 8) + nt * 8 + (lane & 3) * 2;
                float v0 = acc[mg][nt][rr * 2]     + bias[col];
                float v1 = acc[mg][nt][rr * 2 + 1] + bias[col + 1];
                if (DEG) { v0 += dg * g_v[col]; v1 += dg * g_v[col + 1]; }
                if (ACT == 1) { v0 = fmaxf(v0, 0.f); v1 = fmaxf(v1, 0.f); }
                if (ACT == 2) { v0 = tanhf(v0); v1 = tanhf(v1); }
                size_t off = (size_t)row * NOUT + col;
                if (CSEL == 0) {
                    uint32_t hw, lw;
                    split2(v0, v1, hw, lw);
                    *(uint32_t*)&g_ah[off] = hw;
                    *(uint32_t*)&g_al[off] = lw;
                } else if (CSEL == 1) {
                    *(float2*)(g_h + off) = make_float2(v0, v1);
                    uint32_t hw, lw;
                    split2(v0, v1, hw, lw);
                    *(uint32_t*)&g_hh[off] = hw;
                    *(uint32_t*)&g_hl[off] = lw;
                } else {
                    *(float2*)(Cparam + off) = make_float2(v0, v1);
                }
            }
        }
    }
}

// ---------------- launch ----------------
extern "C" void kernel_launch(void* const* d_in, const int* in_sizes, int n_in,
                              void* d_out, int out_size) {
    (void)in_sizes; (void)n_in; (void)out_size;
    const float* x      = (const float*)d_in[0];
    const int*   ei     = (const int*)d_in[1];
    const float* enc_w1 = (const float*)d_in[3];
    const float* enc_b1 = (const float*)d_in[4];
    const float* enc_w2 = (const float*)d_in[5];
    const float* enc_b2 = (const float*)d_in[6];
    const float* msg_w  = (const float*)d_in[7];
    const float* msg_b  = (const float*)d_in[8];
    const float* dec_w1 = (const float*)d_in[9];
    const float* dec_b1 = (const float*)d_in[10];
    const float* dec_w2 = (const float*)d_in[11];
    const float* dec_b2 = (const float*)d_in[12];
    float* out = (float*)d_out;

    const int SM256 = 32768 + 2 * 256 * 128 + 32768 + 2 * 256 * 128; // 2 stages @ 96KB
    const int SM128 = 2 * (32768 + 2 * 128 * 128);                   // 2 stages @ 64KB
    cudaFuncSetAttribute(mm_gemm<1, 0, 0, 0, 0, 256>, cudaFuncAttributeMaxDynamicSharedMemorySize, SM256);
    cudaFuncSetAttribute(mm_gemm<1, 1, 1, 1, 0, 256>, cudaFuncAttributeMaxDynamicSharedMemorySize, SM256);
    cudaFuncSetAttribute(mm_gemm<1, 2, 2, 0, 1, 256>, cudaFuncAttributeMaxDynamicSharedMemorySize, SM256);
    cudaFuncSetAttribute(mm_gemm<2, 1, 3, 2, 0, 128>, cudaFuncAttributeMaxDynamicSharedMemorySize, SM128);

    split_all_kernel<<<BX + 64 + 128 + 64 + 196, 256>>>(x, enc_w1, enc_w2, dec_w2);
    combine_kernel<<<HH, HH>>>(dec_w1, msg_w, msg_b);
    hist_kernel<<<(EE + 255) / 256, 256>>>(ei);
    scan1_kernel<<<NB, 256>>>();
    scan2_kernel<<<1, 256>>>();
    scan3_kernel<<<NB, 256>>>();
    scatter_kernel<<<(EE + 255) / 256, 256>>>(ei);

    const int MT = (NN + 127) / 128;   // 391 M-tiles

    // enc1: h1-split = relu(x @ enc_w1^T + b1), K=128
    mm_gemm<1, 0, 0, 0, 0, 256><<<MT, 256, SM256>>>(DD, enc_b1, nullptr, NN);
    // enc2: g_h fp32 + h-split = relu(h1 @ enc_w2^T + b2), K=256
    mm_gemm<1, 1, 1, 1, 0, 256><<<MT, 256, SM256>>>(HH, enc_b2, nullptr, NN);
    // agg-split = sum_{edges} h[src]
    aggregate_kernel<<<(NN * 32 + 255) / 256, 256>>>();
    // dec1: d-split = relu(agg @ Wc^T + h @ dec_w1b^T + deg*v + b1), K=512 dual-A
    mm_gemm<1, 2, 2, 0, 1, 256><<<MT, 256, SM256>>>(2 * HH, dec_b1, nullptr, NN);
    // dec2: out = tanh(d @ dec_w2^T + b2), K=256, NOUT=128
    mm_gemm<2, 1, 3, 2, 0, 128><<<MT, 256, SM128>>>(HH, dec_b2, out, NN);
}

// round 14
// speedup vs baseline: 2.9306x; 1.2388x over previous
#include <cuda_runtime.h>
#include <cuda_fp16.h>
#include <cstdint>
#include <math.h>

#define NN 50000
#define EE 400000
#define DD 128
#define HH 256
#define NB 196    // ceil(NN/256)
#define NP 50048  // NN padded to 128-row tiles

// ---------------- scratch (static device globals) ----------------
__device__ float g_v   [HH];
__device__ int   g_deg [NN];
__device__ int   g_fill[NN];
__device__ int   g_rowptr[NN + 1];
__device__ int   g_esrc[EE];
__device__ int   g_bsum[NB];
// fp16 operands: A-side split hi/lo, B-side (weights) single fp16
__device__ __half g_xh[NP * DD], g_xl[NP * DD];     // x split
__device__ __half g_ah[NP * HH], g_al[NP * HH];     // h1 split, reused as d split
__device__ __half g_hh[NP * HH], g_hl[NP * HH];     // h split (enc2 out; aggregate input)
__device__ __half g_gh[NP * HH], g_gl[NP * HH];     // agg split
__device__ __half g_w1h[HH * DD];                   // enc_w1 fp16
__device__ __half g_w2h[HH * HH];                   // enc_w2 fp16
__device__ __half g_bch[HH * 2 * HH];               // [Wc | dec_w1b] fp16
__device__ __half g_w3h[DD * HH];                   // dec_w2 fp16

// ---------------- helpers ----------------
__device__ __forceinline__ uint32_t smem_u32(const void* p) {
    uint32_t a;
    asm("{ .reg .u64 t; cvta.to.shared.u64 t, %1; cvt.u32.u64 %0, t; }" : "=r"(a) : "l"(p));
    return a;
}
#define SWZ(off) ((off) ^ (((off) >> 3) & 0x70))

__device__ __forceinline__ void ldsm4(uint32_t* r, uint32_t addr) {
    asm volatile("ldmatrix.sync.aligned.m8n8.x4.shared.b16 {%0,%1,%2,%3}, [%4];"
                 : "=r"(r[0]), "=r"(r[1]), "=r"(r[2]), "=r"(r[3]) : "r"(addr));
}
__device__ __forceinline__ void mma_f16(float* c, const uint32_t* a,
                                        uint32_t b0, uint32_t b1) {
    asm volatile(
        "mma.sync.aligned.m16n8k16.row.col.f32.f16.f16.f32 "
        "{%0,%1,%2,%3}, {%4,%5,%6,%7}, {%8,%9}, {%0,%1,%2,%3};"
        : "+f"(c[0]), "+f"(c[1]), "+f"(c[2]), "+f"(c[3])
        : "r"(a[0]), "r"(a[1]), "r"(a[2]), "r"(a[3]), "r"(b0), "r"(b1));
}
__device__ __forceinline__ void cpa16(uint32_t d, const void* s) {
    asm volatile("cp.async.cg.shared.global [%0], [%1], 16;" :: "r"(d), "l"(s) : "memory");
}
#define CP_COMMIT() asm volatile("cp.async.commit_group;" ::: "memory")

__device__ __forceinline__ uint32_t pkh2(__half a, __half b) {
    __half2 p = __halves2half2(a, b);
    return *reinterpret_cast<uint32_t*>(&p);
}
// split float pair -> fp16 hi word + fp16 lo word
__device__ __forceinline__ void split2h(float v0, float v1, uint32_t& hw, uint32_t& lw) {
    __half h0 = __float2half_rn(v0);
    __half h1 = __float2half_rn(v1);
    __half l0 = __float2half_rn(v0 - __half2float(h0));
    __half l1 = __float2half_rn(v1 - __half2float(h1));
    hw = pkh2(h0, h1);
    lw = pkh2(l0, l1);
}
// round float pair -> single fp16 word
__device__ __forceinline__ uint32_t rnd2h(float v0, float v1) {
    return pkh2(__float2half_rn(v0), __float2half_rn(v1));
}

// ---------------- fused one-shot splits + counter zeroing (single launch) -----------
// block ranges: [0,BX) x | [BX,+64) w1 | [+128) w2 | [+64) w3 | [+196) zero
#define BX (NP * DD / 2 / 256)   // 12512
__global__ void split_all_kernel(const float* __restrict__ x,
                                 const float* __restrict__ w1,
                                 const float* __restrict__ w2,
                                 const float* __restrict__ w3) {
    int b = blockIdx.x;
    if (b < BX) {
        int i = b * 256 + threadIdx.x;           // pair index
        float v0 = 0.f, v1 = 0.f;
        if (i * 2 + 1 < NN * DD) { v0 = x[i * 2]; v1 = x[i * 2 + 1]; }
        else if (i * 2 < NN * DD) { v0 = x[i * 2]; }
        uint32_t hw, lw;
        split2h(v0, v1, hw, lw);
        *(uint32_t*)&g_xh[i * 2] = hw;
        *(uint32_t*)&g_xl[i * 2] = lw;
        return;
    }
    b -= BX;
    if (b < 64) {            // w1: HH*DD elems, 16384 pairs
        int i = b * 256 + threadIdx.x;
        *(uint32_t*)&g_w1h[i * 2] = rnd2h(w1[i * 2], w1[i * 2 + 1]);
        return;
    }
    b -= 64;
    if (b < 128) {           // w2: HH*HH elems
        int i = b * 256 + threadIdx.x;
        *(uint32_t*)&g_w2h[i * 2] = rnd2h(w2[i * 2], w2[i * 2 + 1]);
        return;
    }
    b -= 128;
    if (b < 64) {            // w3: DD*HH elems
        int i = b * 256 + threadIdx.x;
        *(uint32_t*)&g_w3h[i * 2] = rnd2h(w3[i * 2], w3[i * 2 + 1]);
        return;
    }
    b -= 64;
    {                        // zero deg/fill
        int i = b * 256 + threadIdx.x;
        if (i < NN) { g_deg[i] = 0; g_fill[i] = 0; }
    }
}

// ---------------- combine: fold msg GEMM; writes fp16 [Wc | dec_w1b] + g_v ----------
__global__ void combine_kernel(const float* __restrict__ dec_w1,
                               const float* __restrict__ msg_w,
                               const float* __restrict__ msg_b) {
    int i = blockIdx.x;     // 0..255 (output row)
    int k = threadIdx.x;    // 0..255
    __shared__ float srow[HH];
    __shared__ float wcs[HH];
    srow[k] = dec_w1[i * 2 * HH + k];
    __syncthreads();
    float sum = 0.f;
    #pragma unroll 8
    for (int j = 0; j < HH; j++)
        sum = fmaf(srow[j], msg_w[j * HH + k], sum);
    wcs[k] = sum;

    __shared__ float red[HH];
    red[k] = srow[k] * msg_b[k];
    __syncthreads();

    if (k < 128) {
        *(uint32_t*)&g_bch[i * 2 * HH + 2 * k] = rnd2h(wcs[2 * k], wcs[2 * k + 1]);
    } else {
        int j = 2 * (k - 128);
        *(uint32_t*)&g_bch[i * 2 * HH + HH + j] =
            rnd2h(dec_w1[i * 2 * HH + HH + j], dec_w1[i * 2 * HH + HH + j + 1]);
    }

    for (int off = HH / 2; off > 0; off >>= 1) {
        if (k < off) red[k] += red[k + off];
        __syncthreads();
    }
    if (k == 0) g_v[i] = red[0];
}

// ---------------- CSR build ----------------
__global__ void hist_kernel(const int* __restrict__ ei) {
    int e = blockIdx.x * blockDim.x + threadIdx.x;
    if (e < EE) {
        int dd = ei[EE + e];
        if (dd >= 0 && dd < NN) atomicAdd(&g_deg[dd], 1);
    }
}
__global__ void scan1_kernel() {
    __shared__ int sm[256];
    int t = threadIdx.x;
    int idx = blockIdx.x * 256 + t;
    sm[t] = (idx < NN) ? g_deg[idx] : 0;
    __syncthreads();
    for (int off = 128; off > 0; off >>= 1) {
        if (t < off) sm[t] += sm[t + off];
        __syncthreads();
    }
    if (t == 0) g_bsum[blockIdx.x] = sm[0];
}
__global__ void scan2_kernel() {
    int t = threadIdx.x;
    int v = (t < NB) ? g_bsum[t] : 0;
    __shared__ int sm[256];
    sm[t] = v;
    __syncthreads();
    for (int off = 1; off < 256; off <<= 1) {
        int u = (t >= off) ? sm[t - off] : 0;
        __syncthreads();
        sm[t] += u;
        __syncthreads();
    }
    if (t < NB) g_bsum[t] = sm[t] - v;
}
__global__ void scan3_kernel() {
    __shared__ int sm[256];
    int t = threadIdx.x;
    int idx = blockIdx.x * 256 + t;
    int v = (idx < NN) ? g_deg[idx] : 0;
    sm[t] = v;
    __syncthreads();
    for (int off = 1; off < 256; off <<= 1) {
        int u = (t >= off) ? sm[t - off] : 0;
        __syncthreads();
        sm[t] += u;
        __syncthreads();
    }
    if (idx <= NN) g_rowptr[idx] = g_bsum[blockIdx.x] + sm[t] - v;
}
__global__ void scatter_kernel(const int* __restrict__ ei) {
    int e = blockIdx.x * blockDim.x + threadIdx.x;
    if (e < EE) {
        int dd = ei[EE + e];
        if (dd >= 0 && dd < NN) {
            int pos = g_rowptr[dd] + atomicAdd(&g_fill[dd], 1);
            g_esrc[pos] = ei[e];
        }
    }
}

// ------- aggregation: warp per node; reads fp16 hi/lo h, writes fp16 hi/lo agg ------
__global__ void aggregate_kernel() {
    int warp = (blockIdx.x * blockDim.x + threadIdx.x) >> 5;
    int lane = threadIdx.x & 31;
    if (warp >= NN) return;
    int s0 = g_rowptr[warp], s1 = g_rowptr[warp + 1];
    float acc[8] = {0.f, 0.f, 0.f, 0.f, 0.f, 0.f, 0.f, 0.f};
    for (int e = s0; e < s1; e++) {
        size_t rb = (size_t)g_esrc[e] * HH + lane * 8;
        uint4 uh = __ldg((const uint4*)(g_hh + rb));
        uint4 ul = __ldg((const uint4*)(g_hl + rb));
        const __half2* ph = (const __half2*)&uh;
        const __half2* pl = (const __half2*)&ul;
        #pragma unroll
        for (int q = 0; q < 4; q++) {
            float2 fh = __half22float2(ph[q]);
            float2 fl = __half22float2(pl[q]);
            acc[2 * q]     += fh.x + fl.x;
            acc[2 * q + 1] += fh.y + fl.y;
        }
    }
    size_t base = (size_t)warp * HH + lane * 8;
    #pragma unroll
    for (int q = 0; q < 4; q++) {
        uint32_t hw, lw;
        split2h(acc[2 * q], acc[2 * q + 1], hw, lw);
        *(uint32_t*)&g_gh[base + 2 * q] = hw;
        *(uint32_t*)&g_gl[base + 2 * q] = lw;
    }
}

// ====== fp16 2-term tensor GEMM: C = act(A @ Bh^T + bias [+ deg*v]) =================
// A exact as fp16 hi+lo (2 terms: Ah.Bh + Al.Bh); B rounded to fp16 once (pre-split).
// Block: 128 rows x NOUT cols, 8 warps (wm: 2 row groups of 64, wn: 4 col groups).
// K-chunks of 64, 2-stage cp.async double buffer.
// ASEL: 0 = x-split (KA=128), 1 = a-split (KA=256), 2 = dual [g-split | h-split]
// BSEL: 0 = w1, 1 = w2, 2 = bcat, 3 = w3
// CSEL: 0 = a-split, 1 = h-split, 2 = Cparam fp32
template<int ACT, int ASEL, int BSEL, int CSEL, int DEG, int NOUT>
__global__ void __launch_bounds__(256, 1)
mm_gemm(int K, const float* __restrict__ bias, float* __restrict__ Cparam, int M)
{
    constexpr int NT = NOUT / 32;                  // n8 tiles per warp (8 or 4)
    constexpr int OFF_AH = 0, OFF_AL = 16384, OFF_B = 32768;
    constexpr int STAGE_BYTES = 32768 + NOUT * 128;
    constexpr int KA = (ASEL == 0) ? DD : HH;

    extern __shared__ char smem[];
    const uint32_t sb = smem_u32(smem);
    const int tid  = threadIdx.x;
    const int wid  = tid >> 5;
    const int lane = tid & 31;
    const int wm   = wid & 1;       // row group (64 rows)
    const int wn   = wid >> 1;      // col group (NT*8 cols)

    const __half* Bh_;
    if (BSEL == 0)      Bh_ = g_w1h;
    else if (BSEL == 1) Bh_ = g_w2h;
    else if (BSEL == 2) Bh_ = g_bch;
    else                Bh_ = g_w3h;

    const int bm = blockIdx.x * 128;
    const int NC = K / 64;

    // ---- stage issue (chunk c -> buffer c&1) ----
    auto issue = [&](int c) {
        int kc = c * 64;
        uint32_t base = sb + (uint32_t)(c & 1) * STAGE_BYTES;
        const __half *Ah_, *Al_;
        int kcc = kc;
        if (ASEL == 0)      { Ah_ = g_xh; Al_ = g_xl; }
        else if (ASEL == 1) { Ah_ = g_ah; Al_ = g_al; }
        else {
            if (kc < HH) { Ah_ = g_gh; Al_ = g_gl; }
            else         { Ah_ = g_hh; Al_ = g_hl; kcc = kc - HH; }
        }
        #pragma unroll
        for (int i = tid; i < 1024; i += 256) {        // A: 128 rows x 8 units
            int row = i >> 3, unit = i & 7;
            uint32_t sw = SWZ((uint32_t)(row * 128 + unit * 16));
            size_t go = (size_t)(bm + row) * KA + kcc + unit * 8;
            cpa16(base + OFF_AH + sw, Ah_ + go);
            cpa16(base + OFF_AL + sw, Al_ + go);
        }
        #pragma unroll
        for (int i = tid; i < NOUT * 8; i += 256) {    // B: NOUT rows x 8 units
            int row = i >> 3, unit = i & 7;
            uint32_t sw = SWZ((uint32_t)(row * 128 + unit * 16));
            size_t go = (size_t)row * K + kc + unit * 8;
            cpa16(base + OFF_B + sw, Bh_ + go);
        }
        CP_COMMIT();
    };

    float acc[4][NT][4];
    #pragma unroll
    for (int mg = 0; mg < 4; mg++)
        #pragma unroll
        for (int nt = 0; nt < NT; nt++)
            #pragma unroll
            for (int q = 0; q < 4; q++) acc[mg][nt][q] = 0.f;

    issue(0);
    for (int c = 0; c < NC; c++) {
        if (c + 1 < NC) {
            issue(c + 1);
            asm volatile("cp.async.wait_group 1;" ::: "memory");
        } else {
            asm volatile("cp.async.wait_group 0;" ::: "memory");
        }
        __syncthreads();

        uint32_t base = sb + (uint32_t)(c & 1) * STAGE_BYTES;
        #pragma unroll
        for (int kk = 0; kk < 64; kk += 16) {
            uint32_t ah[4][4], al[4][4];
            #pragma unroll
            for (int mg = 0; mg < 4; mg++) {
                int row = wm * 64 + mg * 16 + (lane & 15);
                int bc  = kk * 2 + ((lane >> 4) << 4);
                uint32_t sw = SWZ((uint32_t)(row * 128 + bc));
                ldsm4(ah[mg], base + OFF_AH + sw);
                ldsm4(al[mg], base + OFF_AL + sw);
            }
            uint32_t bh[NT / 2][4];
            #pragma unroll
            for (int np = 0; np < NT / 2; np++) {
                int nrow = wn * (NT * 8) + np * 16 + ((lane >> 4) << 3) + (lane & 7);
                int bc   = kk * 2 + (((lane >> 3) & 1) << 4);
                uint32_t sw = SWZ((uint32_t)(nrow * 128 + bc));
                ldsm4(bh[np], base + OFF_B + sw);
            }
            #pragma unroll
            for (int mg = 0; mg < 4; mg++)
                #pragma unroll
                for (int nt = 0; nt < NT; nt++) {
                    int np = nt >> 1, hb = (nt & 1) * 2;
                    mma_f16(acc[mg][nt], ah[mg], bh[np][hb], bh[np][hb + 1]);
                    mma_f16(acc[mg][nt], al[mg], bh[np][hb], bh[np][hb + 1]);
                }
        }
        __syncthreads();
    }

    // ---- epilogue ----
    #pragma unroll
    for (int mg = 0; mg < 4; mg++) {
        int r0 = bm + wm * 64 + mg * 16 + (lane >> 2);
        #pragma unroll
        for (int rr = 0; rr < 2; rr++) {
            int row = r0 + rr * 8;
            if (row >= M) continue;
            float dg = DEG ? (float)g_deg[row] : 0.f;
            #pragma unroll
            for (int nt = 0; nt < NT; nt++) {
                int col = wn * (NT * 8) + nt * 8 + (lane & 3) * 2;
                float v0 = acc[mg][nt][rr * 2]     + bias[col];
                float v1 = acc[mg][nt][rr * 2 + 1] + bias[col + 1];
                if (DEG) { v0 += dg * g_v[col]; v1 += dg * g_v[col + 1]; }
                if (ACT == 1) { v0 = fmaxf(v0, 0.f); v1 = fmaxf(v1, 0.f); }
                if (ACT == 2) { v0 = tanhf(v0); v1 = tanhf(v1); }
                size_t off = (size_t)row * NOUT + col;
                if (CSEL == 0) {
                    uint32_t hw, lw;
                    split2h(v0, v1, hw, lw);
                    *(uint32_t*)&g_ah[off] = hw;
                    *(uint32_t*)&g_al[off] = lw;
                } else if (CSEL == 1) {
                    uint32_t hw, lw;
                    split2h(v0, v1, hw, lw);
                    *(uint32_t*)&g_hh[off] = hw;
                    *(uint32_t*)&g_hl[off] = lw;
                } else {
                    *(float2*)(Cparam + off) = make_float2(v0, v1);
                }
            }
        }
    }
}

// ---------------- launch ----------------
extern "C" void kernel_launch(void* const* d_in, const int* in_sizes, int n_in,
                              void* d_out, int out_size) {
    (void)in_sizes; (void)n_in; (void)out_size;
    const float* x      = (const float*)d_in[0];
    const int*   ei     = (const int*)d_in[1];
    const float* enc_w1 = (const float*)d_in[3];
    const float* enc_b1 = (const float*)d_in[4];
    const float* enc_w2 = (const float*)d_in[5];
    const float* enc_b2 = (const float*)d_in[6];
    const float* msg_w  = (const float*)d_in[7];
    const float* msg_b  = (const float*)d_in[8];
    const float* dec_w1 = (const float*)d_in[9];
    const float* dec_b1 = (const float*)d_in[10];
    const float* dec_w2 = (const float*)d_in[11];
    const float* dec_b2 = (const float*)d_in[12];
    float* out = (float*)d_out;

    const int SM256 = 2 * (32768 + 256 * 128);   // 2 stages @ 64KB = 128KB
    const int SM128 = 2 * (32768 + 128 * 128);   // 2 stages @ 48KB = 96KB
    cudaFuncSetAttribute(mm_gemm<1, 0, 0, 0, 0, 256>, cudaFuncAttributeMaxDynamicSharedMemorySize, SM256);
    cudaFuncSetAttribute(mm_gemm<1, 1, 1, 1, 0, 256>, cudaFuncAttributeMaxDynamicSharedMemorySize, SM256);
    cudaFuncSetAttribute(mm_gemm<1, 2, 2, 0, 1, 256>, cudaFuncAttributeMaxDynamicSharedMemorySize, SM256);
    cudaFuncSetAttribute(mm_gemm<2, 1, 3, 2, 0, 128>, cudaFuncAttributeMaxDynamicSharedMemorySize, SM128);

    split_all_kernel<<<BX + 64 + 128 + 64 + 196, 256>>>(x, enc_w1, enc_w2, dec_w2);
    combine_kernel<<<HH, HH>>>(dec_w1, msg_w, msg_b);
    hist_kernel<<<(EE + 255) / 256, 256>>>(ei);
    scan1_kernel<<<NB, 256>>>();
    scan2_kernel<<<1, 256>>>();
    scan3_kernel<<<NB, 256>>>();
    scatter_kernel<<<(EE + 255) / 256, 256>>>(ei);

    const int MT = (NN + 127) / 128;   // 391 M-tiles

    // enc1: h1-split = relu(x @ enc_w1^T + b1), K=128
    mm_gemm<1, 0, 0, 0, 0, 256><<<MT, 256, SM256>>>(DD, enc_b1, nullptr, NN);
    // enc2: h-split = relu(h1 @ enc_w2^T + b2), K=256
    mm_gemm<1, 1, 1, 1, 0, 256><<<MT, 256, SM256>>>(HH, enc_b2, nullptr, NN);
    // agg-split = sum_{edges} h[src]
    aggregate_kernel<<<(NN * 32 + 255) / 256, 256>>>();
    // dec1: d-split = relu(agg @ Wc^T + h @ dec_w1b^T + deg*v + b1), K=512 dual-A
    mm_gemm<1, 2, 2, 0, 1, 256><<<MT, 256, SM256>>>(2 * HH, dec_b1, nullptr, NN);
    // dec2: out = tanh(d @ dec_w2^T + b2), K=256, NOUT=128
    mm_gemm<2, 1, 3, 2, 0, 128><<<MT, 256, SM128>>>(HH, dec_b2, out, NN);
}

// round 15
// speedup vs baseline: 3.0514x; 1.0412x over previous
#include <cuda_runtime.h>
#include <cuda_fp16.h>
#include <cstdint>
#include <math.h>

#define NN 50000
#define EE 400000
#define DD 128
#define HH 256
#define NB 196    // ceil(NN/256)
#define NP 50048  // NN padded to 128-row tiles

// ---------------- scratch (static device globals) ----------------
__device__ float g_v   [HH];
__device__ int   g_deg [NN];
__device__ int   g_fill[NN];
__device__ int   g_rowptr[NN + 1];
__device__ int   g_esrc[EE];
__device__ int   g_bsum[NB];
// fp16 operands: A-side split hi/lo, B-side (weights) single fp16
__device__ __half g_xh[NP * DD], g_xl[NP * DD];     // x split
__device__ __half g_ah[NP * HH], g_al[NP * HH];     // h1 split, reused as d split
__device__ __half g_hh[NP * HH], g_hl[NP * HH];     // h split (enc2 out; aggregate input)
__device__ __half g_gh[NP * HH], g_gl[NP * HH];     // agg split
__device__ __half g_w1h[HH * DD];                   // enc_w1 fp16
__device__ __half g_w2h[HH * HH];                   // enc_w2 fp16
__device__ __half g_bch[HH * 2 * HH];               // [Wc | dec_w1b] fp16
__device__ __half g_w3h[DD * HH];                   // dec_w2 fp16

// ---------------- helpers ----------------
__device__ __forceinline__ uint32_t smem_u32(const void* p) {
    uint32_t a;
    asm("{ .reg .u64 t; cvta.to.shared.u64 t, %1; cvt.u32.u64 %0, t; }" : "=r"(a) : "l"(p));
    return a;
}
#define SWZ(off) ((off) ^ (((off) >> 3) & 0x70))

__device__ __forceinline__ void ldsm4(uint32_t* r, uint32_t addr) {
    asm volatile("ldmatrix.sync.aligned.m8n8.x4.shared.b16 {%0,%1,%2,%3}, [%4];"
                 : "=r"(r[0]), "=r"(r[1]), "=r"(r[2]), "=r"(r[3]) : "r"(addr));
}
__device__ __forceinline__ void mma_f16(float* c, const uint32_t* a,
                                        uint32_t b0, uint32_t b1) {
    asm volatile(
        "mma.sync.aligned.m16n8k16.row.col.f32.f16.f16.f32 "
        "{%0,%1,%2,%3}, {%4,%5,%6,%7}, {%8,%9}, {%0,%1,%2,%3};"
        : "+f"(c[0]), "+f"(c[1]), "+f"(c[2]), "+f"(c[3])
        : "r"(a[0]), "r"(a[1]), "r"(a[2]), "r"(a[3]), "r"(b0), "r"(b1));
}
__device__ __forceinline__ void cpa16(uint32_t d, const void* s) {
    asm volatile("cp.async.cg.shared.global [%0], [%1], 16;" :: "r"(d), "l"(s) : "memory");
}
#define CP_COMMIT() asm volatile("cp.async.commit_group;" ::: "memory")

__device__ __forceinline__ uint32_t pkh2(__half a, __half b) {
    __half2 p = __halves2half2(a, b);
    return *reinterpret_cast<uint32_t*>(&p);
}
__device__ __forceinline__ void split2h(float v0, float v1, uint32_t& hw, uint32_t& lw) {
    __half h0 = __float2half_rn(v0);
    __half h1 = __float2half_rn(v1);
    __half l0 = __float2half_rn(v0 - __half2float(h0));
    __half l1 = __float2half_rn(v1 - __half2float(h1));
    hw = pkh2(h0, h1);
    lw = pkh2(l0, l1);
}
__device__ __forceinline__ uint32_t rnd2h(float v0, float v1) {
    return pkh2(__float2half_rn(v0), __float2half_rn(v1));
}

// ---------------- fused one-shot splits + counter zeroing (single launch) -----------
// block ranges: [0,BX) x | [BX,+64) w1 | [+128) w2 | [+64) w3 | [+196) zero
#define BX (NP * DD / 2 / 256)   // 12512
__global__ void split_all_kernel(const float* __restrict__ x,
                                 const float* __restrict__ w1,
                                 const float* __restrict__ w2,
                                 const float* __restrict__ w3) {
    int b = blockIdx.x;
    if (b < BX) {
        int i = b * 256 + threadIdx.x;           // pair index
        float v0 = 0.f, v1 = 0.f;
        if (i * 2 + 1 < NN * DD) { v0 = x[i * 2]; v1 = x[i * 2 + 1]; }
        else if (i * 2 < NN * DD) { v0 = x[i * 2]; }
        uint32_t hw, lw;
        split2h(v0, v1, hw, lw);
        *(uint32_t*)&g_xh[i * 2] = hw;
        *(uint32_t*)&g_xl[i * 2] = lw;
        return;
    }
    b -= BX;
    if (b < 64) {            // w1
        int i = b * 256 + threadIdx.x;
        *(uint32_t*)&g_w1h[i * 2] = rnd2h(w1[i * 2], w1[i * 2 + 1]);
        return;
    }
    b -= 64;
    if (b < 128) {           // w2
        int i = b * 256 + threadIdx.x;
        *(uint32_t*)&g_w2h[i * 2] = rnd2h(w2[i * 2], w2[i * 2 + 1]);
        return;
    }
    b -= 128;
    if (b < 64) {            // w3
        int i = b * 256 + threadIdx.x;
        *(uint32_t*)&g_w3h[i * 2] = rnd2h(w3[i * 2], w3[i * 2 + 1]);
        return;
    }
    b -= 64;
    {                        // zero deg/fill
        int i = b * 256 + threadIdx.x;
        if (i < NN) { g_deg[i] = 0; g_fill[i] = 0; }
    }
}

// -------- combine (blocks 0..HH) + edge histogram (remaining blocks), fused ---------
__global__ void combine_hist_kernel(const float* __restrict__ dec_w1,
                                    const float* __restrict__ msg_w,
                                    const float* __restrict__ msg_b,
                                    const int* __restrict__ ei) {
    if (blockIdx.x >= HH) {
        int e = (blockIdx.x - HH) * 256 + threadIdx.x;
        if (e < EE) {
            int dd = ei[EE + e];
            if (dd >= 0 && dd < NN) atomicAdd(&g_deg[dd], 1);
        }
        return;
    }
    int i = blockIdx.x;     // output row
    int k = threadIdx.x;
    __shared__ float srow[HH];
    __shared__ float wcs[HH];
    srow[k] = dec_w1[i * 2 * HH + k];
    __syncthreads();
    float sum = 0.f;
    #pragma unroll 8
    for (int j = 0; j < HH; j++)
        sum = fmaf(srow[j], msg_w[j * HH + k], sum);
    wcs[k] = sum;

    __shared__ float red[HH];
    red[k] = srow[k] * msg_b[k];
    __syncthreads();

    if (k < 128) {
        *(uint32_t*)&g_bch[i * 2 * HH + 2 * k] = rnd2h(wcs[2 * k], wcs[2 * k + 1]);
    } else {
        int j = 2 * (k - 128);
        *(uint32_t*)&g_bch[i * 2 * HH + HH + j] =
            rnd2h(dec_w1[i * 2 * HH + HH + j], dec_w1[i * 2 * HH + HH + j + 1]);
    }

    for (int off = HH / 2; off > 0; off >>= 1) {
        if (k < off) red[k] += red[k + off];
        __syncthreads();
    }
    if (k == 0) g_v[i] = red[0];
}

// ---------------- scan: block sums, then per-block prefix (scan2 folded in) ---------
__global__ void scan1_kernel() {
    __shared__ int sm[256];
    int t = threadIdx.x;
    int idx = blockIdx.x * 256 + t;
    sm[t] = (idx < NN) ? g_deg[idx] : 0;
    __syncthreads();
    for (int off = 128; off > 0; off >>= 1) {
        if (t < off) sm[t] += sm[t + off];
        __syncthreads();
    }
    if (t == 0) g_bsum[blockIdx.x] = sm[0];
}
__global__ void scan3_kernel() {
    __shared__ int sm[256];
    int t = threadIdx.x;
    int b = blockIdx.x;
    // block offset = sum of g_bsum[0..b)  (b <= 195 < 256)
    sm[t] = (t < b) ? g_bsum[t] : 0;
    __syncthreads();
    for (int off = 128; off > 0; off >>= 1) {
        if (t < off) sm[t] += sm[t + off];
        __syncthreads();
    }
    int blockoff = sm[0];
    __syncthreads();
    int idx = b * 256 + t;
    int v = (idx < NN) ? g_deg[idx] : 0;
    sm[t] = v;
    __syncthreads();
    for (int off = 1; off < 256; off <<= 1) {
        int u = (t >= off) ? sm[t - off] : 0;
        __syncthreads();
        sm[t] += u;
        __syncthreads();
    }
    if (idx <= NN) g_rowptr[idx] = blockoff + sm[t] - v;
}
__global__ void scatter_kernel(const int* __restrict__ ei) {
    int e = blockIdx.x * blockDim.x + threadIdx.x;
    if (e < EE) {
        int dd = ei[EE + e];
        if (dd >= 0 && dd < NN) {
            int pos = g_rowptr[dd] + atomicAdd(&g_fill[dd], 1);
            g_esrc[pos] = ei[e];
        }
    }
}

// ------- aggregation: warp per node; reads fp16 hi/lo h, writes fp16 hi/lo agg ------
__global__ void aggregate_kernel() {
    int warp = (blockIdx.x * blockDim.x + threadIdx.x) >> 5;
    int lane = threadIdx.x & 31;
    if (warp >= NN) return;
    int s0 = g_rowptr[warp], s1 = g_rowptr[warp + 1];
    float acc[8] = {0.f, 0.f, 0.f, 0.f, 0.f, 0.f, 0.f, 0.f};
    for (int e = s0; e < s1; e++) {
        size_t rb = (size_t)g_esrc[e] * HH + lane * 8;
        uint4 uh = __ldg((const uint4*)(g_hh + rb));
        uint4 ul = __ldg((const uint4*)(g_hl + rb));
        const __half2* ph = (const __half2*)&uh;
        const __half2* pl = (const __half2*)&ul;
        #pragma unroll
        for (int q = 0; q < 4; q++) {
            float2 fh = __half22float2(ph[q]);
            float2 fl = __half22float2(pl[q]);
            acc[2 * q]     += fh.x + fl.x;
            acc[2 * q + 1] += fh.y + fl.y;
        }
    }
    size_t base = (size_t)warp * HH + lane * 8;
    #pragma unroll
    for (int q = 0; q < 4; q++) {
        uint32_t hw, lw;
        split2h(acc[2 * q], acc[2 * q + 1], hw, lw);
        *(uint32_t*)&g_gh[base + 2 * q] = hw;
        *(uint32_t*)&g_gl[base + 2 * q] = lw;
    }
}

// ====== fp16 2-term tensor GEMM, 3-stage cp.async pipeline, 1 sync/chunk ============
// C = act(A @ Bh^T + bias [+ deg*v]);  A exact as fp16 hi+lo, B pre-rounded fp16.
// Block: 128 rows x NOUT cols, 8 warps (wm: 2 row groups of 64, wn: 4 col groups).
// ASEL: 0 = x-split (KA=128), 1 = a-split (KA=256), 2 = dual [g-split | h-split]
// BSEL: 0 = w1, 1 = w2, 2 = bcat, 3 = w3
// CSEL: 0 = a-split, 1 = h-split, 2 = Cparam fp32
template<int ACT, int ASEL, int BSEL, int CSEL, int DEG, int NOUT>
__global__ void __launch_bounds__(256, 1)
mm_gemm(int K, const float* __restrict__ bias, float* __restrict__ Cparam, int M)
{
    constexpr int NT = NOUT / 32;                  // n8 tiles per warp (8 or 4)
    constexpr int OFF_AH = 0, OFF_AL = 16384, OFF_B = 32768;
    constexpr int STAGE_BYTES = 32768 + NOUT * 128;
    constexpr int KA = (ASEL == 0) ? DD : HH;

    extern __shared__ char smem[];
    const uint32_t sb = smem_u32(smem);
    const int tid  = threadIdx.x;
    const int wid  = tid >> 5;
    const int lane = tid & 31;
    const int wm   = wid & 1;       // row group (64 rows)
    const int wn   = wid >> 1;      // col group (NT*8 cols)

    const __half* Bh_;
    if (BSEL == 0)      Bh_ = g_w1h;
    else if (BSEL == 1) Bh_ = g_w2h;
    else if (BSEL == 2) Bh_ = g_bch;
    else                Bh_ = g_w3h;

    const int bm = blockIdx.x * 128;
    const int NC = K / 64;

    // ---- stage issue (chunk c -> buffer c%3) ----
    auto issue = [&](int c) {
        int kc = c * 64;
        uint32_t base = sb + (uint32_t)(c % 3) * STAGE_BYTES;
        const __half *Ah_, *Al_;
        int kcc = kc;
        if (ASEL == 0)      { Ah_ = g_xh; Al_ = g_xl; }
        else if (ASEL == 1) { Ah_ = g_ah; Al_ = g_al; }
        else {
            if (kc < HH) { Ah_ = g_gh; Al_ = g_gl; }
            else         { Ah_ = g_hh; Al_ = g_hl; kcc = kc - HH; }
        }
        #pragma unroll
        for (int i = tid; i < 1024; i += 256) {        // A: 128 rows x 8 units
            int row = i >> 3, unit = i & 7;
            uint32_t sw = SWZ((uint32_t)(row * 128 + unit * 16));
            size_t go = (size_t)(bm + row) * KA + kcc + unit * 8;
            cpa16(base + OFF_AH + sw, Ah_ + go);
            cpa16(base + OFF_AL + sw, Al_ + go);
        }
        #pragma unroll
        for (int i = tid; i < NOUT * 8; i += 256) {    // B: NOUT rows x 8 units
            int row = i >> 3, unit = i & 7;
            uint32_t sw = SWZ((uint32_t)(row * 128 + unit * 16));
            size_t go = (size_t)row * K + kc + unit * 8;
            cpa16(base + OFF_B + sw, Bh_ + go);
        }
        CP_COMMIT();
    };

    float acc[4][NT][4];
    #pragma unroll
    for (int mg = 0; mg < 4; mg++)
        #pragma unroll
        for (int nt = 0; nt < NT; nt++)
            #pragma unroll
            for (int q = 0; q < 4; q++) acc[mg][nt][q] = 0.f;

    issue(0);
    if (NC > 1) issue(1);
    for (int c = 0; c < NC; c++) {
        if (c + 1 < NC) {
            asm volatile("cp.async.wait_group 1;" ::: "memory");
        } else {
            asm volatile("cp.async.wait_group 0;" ::: "memory");
        }
        __syncthreads();
        // prefetch chunk c+2 into buffer (c+2)%3; that buffer was last read in
        // chunk c-1, and every warp passed this chunk's barrier after finishing it.
        if (c + 2 < NC) issue(c + 2);

        uint32_t base = sb + (uint32_t)(c % 3) * STAGE_BYTES;
        #pragma unroll
        for (int kk = 0; kk < 64; kk += 16) {
            uint32_t ah[4][4], al[4][4];
            #pragma unroll
            for (int mg = 0; mg < 4; mg++) {
                int row = wm * 64 + mg * 16 + (lane & 15);
                int bc  = kk * 2 + ((lane >> 4) << 4);
                uint32_t sw = SWZ((uint32_t)(row * 128 + bc));
                ldsm4(ah[mg], base + OFF_AH + sw);
                ldsm4(al[mg], base + OFF_AL + sw);
            }
            uint32_t bh[NT / 2][4];
            #pragma unroll
            for (int np = 0; np < NT / 2; np++) {
                int nrow = wn * (NT * 8) + np * 16 + ((lane >> 4) << 3) + (lane & 7);
                int bc   = kk * 2 + (((lane >> 3) & 1) << 4);
                uint32_t sw = SWZ((uint32_t)(nrow * 128 + bc));
                ldsm4(bh[np], base + OFF_B + sw);
            }
            #pragma unroll
            for (int mg = 0; mg < 4; mg++)
                #pragma unroll
                for (int nt = 0; nt < NT; nt++) {
                    int np = nt >> 1, hb = (nt & 1) * 2;
                    mma_f16(acc[mg][nt], ah[mg], bh[np][hb], bh[np][hb + 1]);
                    mma_f16(acc[mg][nt], al[mg], bh[np][hb], bh[np][hb + 1]);
                }
        }
    }

    // ---- epilogue ----
    #pragma unroll
    for (int mg = 0; mg < 4; mg++) {
        int r0 = bm + wm * 64 + mg * 16 + (lane >> 2);
        #pragma unroll
        for (int rr = 0; rr < 2; rr++) {
            int row = r0 + rr * 8;
            if (row >= M) continue;
            float dg = DEG ? (float)g_deg[row] : 0.f;
            #pragma unroll
            for (int nt = 0; nt < NT; nt++) {
                int col = wn * (NT * 8) + nt * 8 + (lane & 3) * 2;
                float v0 = acc[mg][nt][rr * 2]     + bias[col];
                float v1 = acc[mg][nt][rr * 2 + 1] + bias[col + 1];
                if (DEG) { v0 += dg * g_v[col]; v1 += dg * g_v[col + 1]; }
                if (ACT == 1) { v0 = fmaxf(v0, 0.f); v1 = fmaxf(v1, 0.f); }
                if (ACT == 2) { v0 = tanhf(v0); v1 = tanhf(v1); }
                size_t off = (size_t)row * NOUT + col;
                if (CSEL == 0) {
                    uint32_t hw, lw;
                    split2h(v0, v1, hw, lw);
                    *(uint32_t*)&g_ah[off] = hw;
                    *(uint32_t*)&g_al[off] = lw;
                } else if (CSEL == 1) {
                    uint32_t hw, lw;
                    split2h(v0, v1, hw, lw);
                    *(uint32_t*)&g_hh[off] = hw;
                    *(uint32_t*)&g_hl[off] = lw;
                } else {
                    *(float2*)(Cparam + off) = make_float2(v0, v1);
                }
            }
        }
    }
}

// ---------------- launch ----------------
extern "C" void kernel_launch(void* const* d_in, const int* in_sizes, int n_in,
                              void* d_out, int out_size) {
    (void)in_sizes; (void)n_in; (void)out_size;
    const float* x      = (const float*)d_in[0];
    const int*   ei     = (const int*)d_in[1];
    const float* enc_w1 = (const float*)d_in[3];
    const float* enc_b1 = (const float*)d_in[4];
    const float* enc_w2 = (const float*)d_in[5];
    const float* enc_b2 = (const float*)d_in[6];
    const float* msg_w  = (const float*)d_in[7];
    const float* msg_b  = (const float*)d_in[8];
    const float* dec_w1 = (const float*)d_in[9];
    const float* dec_b1 = (const float*)d_in[10];
    const float* dec_w2 = (const float*)d_in[11];
    const float* dec_b2 = (const float*)d_in[12];
    float* out = (float*)d_out;

    const int SM256 = 3 * (32768 + 256 * 128);   // 3 stages @ 64KB = 192KB
    const int SM128 = 3 * (32768 + 128 * 128);   // 3 stages @ 48KB = 144KB
    cudaFuncSetAttribute(mm_gemm<1, 0, 0, 0, 0, 256>, cudaFuncAttributeMaxDynamicSharedMemorySize, SM256);
    cudaFuncSetAttribute(mm_gemm<1, 1, 1, 1, 0, 256>, cudaFuncAttributeMaxDynamicSharedMemorySize, SM256);
    cudaFuncSetAttribute(mm_gemm<1, 2, 2, 0, 1, 256>, cudaFuncAttributeMaxDynamicSharedMemorySize, SM256);
    cudaFuncSetAttribute(mm_gemm<2, 1, 3, 2, 0, 128>, cudaFuncAttributeMaxDynamicSharedMemorySize, SM128);

    split_all_kernel<<<BX + 64 + 128 + 64 + 196, 256>>>(x, enc_w1, enc_w2, dec_w2);
    combine_hist_kernel<<<HH + (EE + 255) / 256, 256>>>(dec_w1, msg_w, msg_b, ei);
    scan1_kernel<<<NB, 256>>>();
    scan3_kernel<<<NB, 256>>>();
    scatter_kernel<<<(EE + 255) / 256, 256>>>(ei);

    const int MT = (NN + 127) / 128;   // 391 M-tiles

    // enc1: h1-split = relu(x @ enc_w1^T + b1), K=128
    mm_gemm<1, 0, 0, 0, 0, 256><<<MT, 256, SM256>>>(DD, enc_b1, nullptr, NN);
    // enc2: h-split = relu(h1 @ enc_w2^T + b2), K=256
    mm_gemm<1, 1, 1, 1, 0, 256><<<MT, 256, SM256>>>(HH, enc_b2, nullptr, NN);
    // agg-split = sum_{edges} h[src]
    aggregate_kernel<<<(NN * 32 + 255) / 256, 256>>>();
    // dec1: d-split = relu(agg @ Wc^T + h @ dec_w1b^T + deg*v + b1), K=512 dual-A
    mm_gemm<1, 2, 2, 0, 1, 256><<<MT, 256, SM256>>>(2 * HH, dec_b1, nullptr, NN);
    // dec2: out = tanh(d @ dec_w2^T + b2), K=256, NOUT=128
    mm_gemm<2, 1, 3, 2, 0, 128><<<MT, 256, SM128>>>(HH, dec_b2, out, NN);
}

// round 16
// speedup vs baseline: 3.1668x; 1.0378x over previous
#include <cuda_runtime.h>
#include <cuda_fp16.h>
#include <cstdint>
#include <math.h>

#define NN 50000
#define EE 400000
#define DD 128
#define HH 256
#define NB 196    // ceil(NN/256)
#define NP 50048  // NN padded to 128-row tiles

// ---------------- scratch (static device globals) ----------------
__device__ float g_v   [HH];
__device__ int   g_deg [NN];
__device__ int   g_fill[NN];
__device__ int   g_rowptr[NN + 1];
__device__ int   g_esrc[EE];
__device__ int   g_bsum[NB];
// fp16 operands: A-side split hi/lo, B-side (weights) single fp16
__device__ __half g_xh[NP * DD], g_xl[NP * DD];     // x split
__device__ __half g_ah[NP * HH], g_al[NP * HH];     // h1 split, reused as d split
__device__ __half g_hh[NP * HH], g_hl[NP * HH];     // h split (enc2 out; aggregate input)
__device__ __half g_gh[NP * HH], g_gl[NP * HH];     // agg split
__device__ __half g_w1h[HH * DD];                   // enc_w1 fp16
__device__ __half g_w2h[HH * HH];                   // enc_w2 fp16
__device__ __half g_bch[HH * 2 * HH];               // [Wc | dec_w1b] fp16
__device__ __half g_w3h[DD * HH];                   // dec_w2 fp16

// ---------------- helpers ----------------
__device__ __forceinline__ uint32_t smem_u32(const void* p) {
    uint32_t a;
    asm("{ .reg .u64 t; cvta.to.shared.u64 t, %1; cvt.u32.u64 %0, t; }" : "=r"(a) : "l"(p));
    return a;
}
#define SWZ(off) ((off) ^ (((off) >> 3) & 0x70))

__device__ __forceinline__ void ldsm4(uint32_t* r, uint32_t addr) {
    asm volatile("ldmatrix.sync.aligned.m8n8.x4.shared.b16 {%0,%1,%2,%3}, [%4];"
                 : "=r"(r[0]), "=r"(r[1]), "=r"(r[2]), "=r"(r[3]) : "r"(addr));
}
__device__ __forceinline__ void mma_f16(float* c, const uint32_t* a,
                                        uint32_t b0, uint32_t b1) {
    asm volatile(
        "mma.sync.aligned.m16n8k16.row.col.f32.f16.f16.f32 "
        "{%0,%1,%2,%3}, {%4,%5,%6,%7}, {%8,%9}, {%0,%1,%2,%3};"
        : "+f"(c[0]), "+f"(c[1]), "+f"(c[2]), "+f"(c[3])
        : "r"(a[0]), "r"(a[1]), "r"(a[2]), "r"(a[3]), "r"(b0), "r"(b1));
}
__device__ __forceinline__ void cpa16(uint32_t d, const void* s) {
    asm volatile("cp.async.cg.shared.global [%0], [%1], 16;" :: "r"(d), "l"(s) : "memory");
}
#define CP_COMMIT() asm volatile("cp.async.commit_group;" ::: "memory")

__device__ __forceinline__ uint32_t pkh2(__half a, __half b) {
    __half2 p = __halves2half2(a, b);
    return *reinterpret_cast<uint32_t*>(&p);
}
__device__ __forceinline__ void split2h(float v0, float v1, uint32_t& hw, uint32_t& lw) {
    __half h0 = __float2half_rn(v0);
    __half h1 = __float2half_rn(v1);
    __half l0 = __float2half_rn(v0 - __half2float(h0));
    __half l1 = __float2half_rn(v1 - __half2float(h1));
    hw = pkh2(h0, h1);
    lw = pkh2(l0, l1);
}
__device__ __forceinline__ uint32_t rnd2h(float v0, float v1) {
    return pkh2(__float2half_rn(v0), __float2half_rn(v1));
}

// ---------------- fused one-shot splits + counter zeroing (single launch) -----------
// block ranges: [0,BX) x | [BX,+64) w1 | [+128) w2 | [+64) w3 | [+196) zero
#define BX (NP * DD / 2 / 256)   // 12512
__global__ void split_all_kernel(const float* __restrict__ x,
                                 const float* __restrict__ w1,
                                 const float* __restrict__ w2,
                                 const float* __restrict__ w3) {
    int b = blockIdx.x;
    if (b < BX) {
        int i = b * 256 + threadIdx.x;           // pair index
        float v0 = 0.f, v1 = 0.f;
        if (i * 2 + 1 < NN * DD) { v0 = x[i * 2]; v1 = x[i * 2 + 1]; }
        else if (i * 2 < NN * DD) { v0 = x[i * 2]; }
        uint32_t hw, lw;
        split2h(v0, v1, hw, lw);
        *(uint32_t*)&g_xh[i * 2] = hw;
        *(uint32_t*)&g_xl[i * 2] = lw;
        return;
    }
    b -= BX;
    if (b < 64) {            // w1
        int i = b * 256 + threadIdx.x;
        *(uint32_t*)&g_w1h[i * 2] = rnd2h(w1[i * 2], w1[i * 2 + 1]);
        return;
    }
    b -= 64;
    if (b < 128) {           // w2
        int i = b * 256 + threadIdx.x;
        *(uint32_t*)&g_w2h[i * 2] = rnd2h(w2[i * 2], w2[i * 2 + 1]);
        return;
    }
    b -= 128;
    if (b < 64) {            // w3
        int i = b * 256 + threadIdx.x;
        *(uint32_t*)&g_w3h[i * 2] = rnd2h(w3[i * 2], w3[i * 2 + 1]);
        return;
    }
    b -= 64;
    {                        // zero deg/fill
        int i = b * 256 + threadIdx.x;
        if (i < NN) { g_deg[i] = 0; g_fill[i] = 0; }
    }
}

// -------- combine (blocks 0..HH) + edge histogram (remaining blocks), fused ---------
__global__ void combine_hist_kernel(const float* __restrict__ dec_w1,
                                    const float* __restrict__ msg_w,
                                    const float* __restrict__ msg_b,
                                    const int* __restrict__ ei) {
    if (blockIdx.x >= HH) {
        int e = (blockIdx.x - HH) * 256 + threadIdx.x;
        if (e < EE) {
            int dd = ei[EE + e];
            if (dd >= 0 && dd < NN) atomicAdd(&g_deg[dd], 1);
        }
        return;
    }
    int i = blockIdx.x;     // output row
    int k = threadIdx.x;
    __shared__ float srow[HH];
    __shared__ float wcs[HH];
    srow[k] = dec_w1[i * 2 * HH + k];
    __syncthreads();
    float sum = 0.f;
    #pragma unroll 8
    for (int j = 0; j < HH; j++)
        sum = fmaf(srow[j], msg_w[j * HH + k], sum);
    wcs[k] = sum;

    __shared__ float red[HH];
    red[k] = srow[k] * msg_b[k];
    __syncthreads();

    if (k < 128) {
        *(uint32_t*)&g_bch[i * 2 * HH + 2 * k] = rnd2h(wcs[2 * k], wcs[2 * k + 1]);
    } else {
        int j = 2 * (k - 128);
        *(uint32_t*)&g_bch[i * 2 * HH + HH + j] =
            rnd2h(dec_w1[i * 2 * HH + HH + j], dec_w1[i * 2 * HH + HH + j + 1]);
    }

    for (int off = HH / 2; off > 0; off >>= 1) {
        if (k < off) red[k] += red[k + off];
        __syncthreads();
    }
    if (k == 0) g_v[i] = red[0];
}

// ---------------- scan: block sums, then per-block prefix ----------------
__global__ void scan1_kernel() {
    __shared__ int sm[256];
    int t = threadIdx.x;
    int idx = blockIdx.x * 256 + t;
    sm[t] = (idx < NN) ? g_deg[idx] : 0;
    __syncthreads();
    for (int off = 128; off > 0; off >>= 1) {
        if (t < off) sm[t] += sm[t + off];
        __syncthreads();
    }
    if (t == 0) g_bsum[blockIdx.x] = sm[0];
}
__global__ void scan3_kernel() {
    __shared__ int sm[256];
    int t = threadIdx.x;
    int b = blockIdx.x;
    sm[t] = (t < b) ? g_bsum[t] : 0;
    __syncthreads();
    for (int off = 128; off > 0; off >>= 1) {
        if (t < off) sm[t] += sm[t + off];
        __syncthreads();
    }
    int blockoff = sm[0];
    __syncthreads();
    int idx = b * 256 + t;
    int v = (idx < NN) ? g_deg[idx] : 0;
    sm[t] = v;
    __syncthreads();
    for (int off = 1; off < 256; off <<= 1) {
        int u = (t >= off) ? sm[t - off] : 0;
        __syncthreads();
        sm[t] += u;
        __syncthreads();
    }
    if (idx <= NN) g_rowptr[idx] = blockoff + sm[t] - v;
}
__global__ void scatter_kernel(const int* __restrict__ ei) {
    int e = blockIdx.x * blockDim.x + threadIdx.x;
    if (e < EE) {
        int dd = ei[EE + e];
        if (dd >= 0 && dd < NN) {
            int pos = g_rowptr[dd] + atomicAdd(&g_fill[dd], 1);
            g_esrc[pos] = ei[e];
        }
    }
}

// ------- aggregation: warp per node; reads fp16 hi/lo h, writes fp16 hi/lo agg ------
__global__ void aggregate_kernel() {
    int warp = (blockIdx.x * blockDim.x + threadIdx.x) >> 5;
    int lane = threadIdx.x & 31;
    if (warp >= NN) return;
    int s0 = g_rowptr[warp], s1 = g_rowptr[warp + 1];
    float acc[8] = {0.f, 0.f, 0.f, 0.f, 0.f, 0.f, 0.f, 0.f};
    for (int e = s0; e < s1; e++) {
        size_t rb = (size_t)g_esrc[e] * HH + lane * 8;
        uint4 uh = __ldg((const uint4*)(g_hh + rb));
        uint4 ul = __ldg((const uint4*)(g_hl + rb));
        const __half2* ph = (const __half2*)&uh;
        const __half2* pl = (const __half2*)&ul;
        #pragma unroll
        for (int q = 0; q < 4; q++) {
            float2 fh = __half22float2(ph[q]);
            float2 fl = __half22float2(pl[q]);
            acc[2 * q]     += fh.x + fl.x;
            acc[2 * q + 1] += fh.y + fl.y;
        }
    }
    size_t base = (size_t)warp * HH + lane * 8;
    #pragma unroll
    for (int q = 0; q < 4; q++) {
        uint32_t hw, lw;
        split2h(acc[2 * q], acc[2 * q + 1], hw, lw);
        *(uint32_t*)&g_gh[base + 2 * q] = hw;
        *(uint32_t*)&g_gl[base + 2 * q] = lw;
    }
}

// ====== fp16 2-term tensor GEMM, 3-stage cp.async pipeline, 1 sync/chunk ============
// C = act(A @ Bh^T + bias [+ deg*v]);  A exact as fp16 hi+lo, B pre-rounded fp16.
// Block: 128 rows x NOUT cols, 8 warps (wm: 2 row groups of 64, wn: 4 col groups).
// ASEL: 0 = x-split (KA=128), 1 = a-split (KA=256), 2 = dual [g-split | h-split]
// BSEL: 0 = w1, 1 = w2, 2 = bcat, 3 = w3
// CSEL: 0 = a-split, 1 = h-split, 2 = Cparam fp32
template<int ACT, int ASEL, int BSEL, int CSEL, int DEG, int NOUT>
__global__ void __launch_bounds__(256, 1)
mm_gemm(int K, const float* __restrict__ bias, float* __restrict__ Cparam, int M)
{
    constexpr int NT = NOUT / 32;                  // n8 tiles per warp (8 or 4)
    constexpr int OFF_AH = 0, OFF_AL = 16384, OFF_B = 32768;
    constexpr int STAGE_BYTES = 32768 + NOUT * 128;
    constexpr int KA = (ASEL == 0) ? DD : HH;

    extern __shared__ char smem[];
    const uint32_t sb = smem_u32(smem);
    const int tid  = threadIdx.x;
    const int wid  = tid >> 5;
    const int lane = tid & 31;
    const int wm   = wid & 1;       // row group (64 rows)
    const int wn   = wid >> 1;      // col group (NT*8 cols)

    const __half* Bh_;
    if (BSEL == 0)      Bh_ = g_w1h;
    else if (BSEL == 1) Bh_ = g_w2h;
    else if (BSEL == 2) Bh_ = g_bch;
    else                Bh_ = g_w3h;

    const int bm = blockIdx.x * 128;
    const int NC = K / 64;

    // ---- stage issue (chunk c -> buffer c%3) ----
    auto issue = [&](int c) {
        int kc = c * 64;
        uint32_t base = sb + (uint32_t)(c % 3) * STAGE_BYTES;
        const __half *Ah_, *Al_;
        int kcc = kc;
        if (ASEL == 0)      { Ah_ = g_xh; Al_ = g_xl; }
        else if (ASEL == 1) { Ah_ = g_ah; Al_ = g_al; }
        else {
            if (kc < HH) { Ah_ = g_gh; Al_ = g_gl; }
            else         { Ah_ = g_hh; Al_ = g_hl; kcc = kc - HH; }
        }
        #pragma unroll
        for (int i = tid; i < 1024; i += 256) {        // A: 128 rows x 8 units
            int row = i >> 3, unit = i & 7;
            uint32_t sw = SWZ((uint32_t)(row * 128 + unit * 16));
            size_t go = (size_t)(bm + row) * KA + kcc + unit * 8;
            cpa16(base + OFF_AH + sw, Ah_ + go);
            cpa16(base + OFF_AL + sw, Al_ + go);
        }
        #pragma unroll
        for (int i = tid; i < NOUT * 8; i += 256) {    // B: NOUT rows x 8 units
            int row = i >> 3, unit = i & 7;
            uint32_t sw = SWZ((uint32_t)(row * 128 + unit * 16));
            size_t go = (size_t)row * K + kc + unit * 8;
            cpa16(base + OFF_B + sw, Bh_ + go);
        }
        CP_COMMIT();
    };

    float acc[4][NT][4];
    #pragma unroll
    for (int mg = 0; mg < 4; mg++)
        #pragma unroll
        for (int nt = 0; nt < NT; nt++)
            #pragma unroll
            for (int q = 0; q < 4; q++) acc[mg][nt][q] = 0.f;

    issue(0);
    if (NC > 1) issue(1);
    for (int c = 0; c < NC; c++) {
        if (c + 1 < NC) {
            asm volatile("cp.async.wait_group 1;" ::: "memory");
        } else {
            asm volatile("cp.async.wait_group 0;" ::: "memory");
        }
        __syncthreads();
        if (c + 2 < NC) issue(c + 2);

        uint32_t base = sb + (uint32_t)(c % 3) * STAGE_BYTES;
        #pragma unroll
        for (int kk = 0; kk < 64; kk += 16) {
            uint32_t ah[4][4], al[4][4];
            #pragma unroll
            for (int mg = 0; mg < 4; mg++) {
                int row = wm * 64 + mg * 16 + (lane & 15);
                int bc  = kk * 2 + ((lane >> 4) << 4);
                uint32_t sw = SWZ((uint32_t)(row * 128 + bc));
                ldsm4(ah[mg], base + OFF_AH + sw);
                ldsm4(al[mg], base + OFF_AL + sw);
            }
            uint32_t bh[NT / 2][4];
            #pragma unroll
            for (int np = 0; np < NT / 2; np++) {
                int nrow = wn * (NT * 8) + np * 16 + ((lane >> 4) << 3) + (lane & 7);
                int bc   = kk * 2 + (((lane >> 3) & 1) << 4);
                uint32_t sw = SWZ((uint32_t)(nrow * 128 + bc));
                ldsm4(bh[np], base + OFF_B + sw);
            }
            #pragma unroll
            for (int mg = 0; mg < 4; mg++)
                #pragma unroll
                for (int nt = 0; nt < NT; nt++) {
                    int np = nt >> 1, hb = (nt & 1) * 2;
                    mma_f16(acc[mg][nt], ah[mg], bh[np][hb], bh[np][hb + 1]);
                    mma_f16(acc[mg][nt], al[mg], bh[np][hb], bh[np][hb + 1]);
                }
        }
    }

    // ---- epilogue ----
    #pragma unroll
    for (int mg = 0; mg < 4; mg++) {
        int r0 = bm + wm * 64 + mg * 16 + (lane >> 2);
        #pragma unroll
        for (int rr = 0; rr < 2; rr++) {
            int row = r0 + rr * 8;
            if (row >= M) continue;
            float dg = DEG ? (float)g_deg[row] : 0.f;
            #pragma unroll
            for (int nt = 0; nt < NT; nt++) {
                int col = wn * (NT * 8) + nt * 8 + (lane & 3) * 2;
                float v0 = acc[mg][nt][rr * 2]     + bias[col];
                float v1 = acc[mg][nt][rr * 2 + 1] + bias[col + 1];
                if (DEG) { v0 += dg * g_v[col]; v1 += dg * g_v[col + 1]; }
                if (ACT == 1) { v0 = fmaxf(v0, 0.f); v1 = fmaxf(v1, 0.f); }
                if (ACT == 2) { v0 = tanhf(v0); v1 = tanhf(v1); }
                size_t off = (size_t)row * NOUT + col;
                if (CSEL == 0) {
                    uint32_t hw, lw;
                    split2h(v0, v1, hw, lw);
                    *(uint32_t*)&g_ah[off] = hw;
                    *(uint32_t*)&g_al[off] = lw;
                } else if (CSEL == 1) {
                    uint32_t hw, lw;
                    split2h(v0, v1, hw, lw);
                    *(uint32_t*)&g_hh[off] = hw;
                    *(uint32_t*)&g_hl[off] = lw;
                } else {
                    *(float2*)(Cparam + off) = make_float2(v0, v1);
                }
            }
        }
    }
}

// ---------------- launch: fork CSR chain onto side stream (capture-safe) ------------
extern "C" void kernel_launch(void* const* d_in, const int* in_sizes, int n_in,
                              void* d_out, int out_size) {
    (void)in_sizes; (void)n_in; (void)out_size;
    const float* x      = (const float*)d_in[0];
    const int*   ei     = (const int*)d_in[1];
    const float* enc_w1 = (const float*)d_in[3];
    const float* enc_b1 = (const float*)d_in[4];
    const float* enc_w2 = (const float*)d_in[5];
    const float* enc_b2 = (const float*)d_in[6];
    const float* msg_w  = (const float*)d_in[7];
    const float* msg_b  = (const float*)d_in[8];
    const float* dec_w1 = (const float*)d_in[9];
    const float* dec_b1 = (const float*)d_in[10];
    const float* dec_w2 = (const float*)d_in[11];
    const float* dec_b2 = (const float*)d_in[12];
    float* out = (float*)d_out;

    const int SM256 = 3 * (32768 + 256 * 128);   // 192KB
    const int SM128 = 3 * (32768 + 128 * 128);   // 144KB
    cudaFuncSetAttribute(mm_gemm<1, 0, 0, 0, 0, 256>, cudaFuncAttributeMaxDynamicSharedMemorySize, SM256);
    cudaFuncSetAttribute(mm_gemm<1, 1, 1, 1, 0, 256>, cudaFuncAttributeMaxDynamicSharedMemorySize, SM256);
    cudaFuncSetAttribute(mm_gemm<1, 2, 2, 0, 1, 256>, cudaFuncAttributeMaxDynamicSharedMemorySize, SM256);
    cudaFuncSetAttribute(mm_gemm<2, 1, 3, 2, 0, 128>, cudaFuncAttributeMaxDynamicSharedMemorySize, SM128);

    // side stream + events; created per call (kernel_launch only runs for the
    // correctness pass and the single capture pass), intentionally not destroyed
    // so no object is torn down while the harness's capture is still open.
    cudaStream_t s2;
    cudaStreamCreateWithFlags(&s2, cudaStreamNonBlocking);
    cudaEvent_t evFork, evJoin;
    cudaEventCreateWithFlags(&evFork, cudaEventDisableTiming);
    cudaEventCreateWithFlags(&evJoin, cudaEventDisableTiming);

    // main stream: splits (also zeroes deg/fill)
    split_all_kernel<<<BX + 64 + 128 + 64 + 196, 256>>>(x, enc_w1, enc_w2, dec_w2);
    cudaEventRecord(evFork, 0);

    // side stream: CSR chain + weight-combine, overlapped with encoder GEMMs
    cudaStreamWaitEvent(s2, evFork, 0);
    combine_hist_kernel<<<HH + (EE + 255) / 256, 256, 0, s2>>>(dec_w1, msg_w, msg_b, ei);
    scan1_kernel<<<NB, 256, 0, s2>>>();
    scan3_kernel<<<NB, 256, 0, s2>>>();
    scatter_kernel<<<(EE + 255) / 256, 256, 0, s2>>>(ei);
    cudaEventRecord(evJoin, s2);

    const int MT = (NN + 127) / 128;   // 391 M-tiles

    // main stream: encoder GEMMs run concurrently with the CSR chain
    mm_gemm<1, 0, 0, 0, 0, 256><<<MT, 256, SM256>>>(DD, enc_b1, nullptr, NN);
    mm_gemm<1, 1, 1, 1, 0, 256><<<MT, 256, SM256>>>(HH, enc_b2, nullptr, NN);

    // join: aggregate needs scatter (s2) + enc2 (main)
    cudaStreamWaitEvent(0, evJoin, 0);
    aggregate_kernel<<<(NN * 32 + 255) / 256, 256>>>();
    // dec1: d-split = relu(agg @ Wc^T + h @ dec_w1b^T + deg*v + b1), K=512 dual-A
    mm_gemm<1, 2, 2, 0, 1, 256><<<MT, 256, SM256>>>(2 * HH, dec_b1, nullptr, NN);
    // dec2: out = tanh(d @ dec_w2^T + b2), K=256, NOUT=128
    mm_gemm<2, 1, 3, 2, 0, 128><<<MT, 256, SM128>>>(HH, dec_b2, out, NN);
}

// round 17
// speedup vs baseline: 3.4251x; 1.0816x over previous
#include <cuda_runtime.h>
#include <cuda_fp16.h>
#include <cstdint>
#include <math.h>

#define NN 50000
#define EE 400000
#define DD 128
#define HH 256
#define NB 196    // ceil(NN/256)
#define NP 50048  // NN padded to 128-row tiles

// ---------------- scratch (static device globals) ----------------
__device__ float g_v   [HH];
__device__ int   g_deg [NN];
__device__ int   g_fill[NN];
__device__ int   g_rowptr[NN + 1];
__device__ int   g_esrc[EE];
__device__ int   g_bsum[NB];
// fp16 operands: A-side split hi/lo, B-side (weights) single fp16
__device__ __half g_xh[NP * DD], g_xl[NP * DD];     // x split
__device__ __half g_ah[NP * HH], g_al[NP * HH];     // h1 split
__device__ __half g_hh[NP * HH], g_hl[NP * HH];     // h split (enc2 out; aggregate input)
__device__ __half g_gh[NP * HH], g_gl[NP * HH];     // agg split
__device__ __half g_w1h[HH * DD];                   // enc_w1 fp16
__device__ __half g_w2h[HH * HH];                   // enc_w2 fp16
__device__ __half g_bch[HH * 2 * HH];               // [Wc | dec_w1b] fp16
__device__ __half g_w3h[DD * HH];                   // dec_w2 fp16

// ---------------- helpers ----------------
__device__ __forceinline__ uint32_t smem_u32(const void* p) {
    uint32_t a;
    asm("{ .reg .u64 t; cvta.to.shared.u64 t, %1; cvt.u32.u64 %0, t; }" : "=r"(a) : "l"(p));
    return a;
}
#define SWZ(off) ((off) ^ (((off) >> 3) & 0x70))

__device__ __forceinline__ void ldsm4(uint32_t* r, uint32_t addr) {
    asm volatile("ldmatrix.sync.aligned.m8n8.x4.shared.b16 {%0,%1,%2,%3}, [%4];"
                 : "=r"(r[0]), "=r"(r[1]), "=r"(r[2]), "=r"(r[3]) : "r"(addr));
}
__device__ __forceinline__ void mma_f16(float* c, const uint32_t* a,
                                        uint32_t b0, uint32_t b1) {
    asm volatile(
        "mma.sync.aligned.m16n8k16.row.col.f32.f16.f16.f32 "
        "{%0,%1,%2,%3}, {%4,%5,%6,%7}, {%8,%9}, {%0,%1,%2,%3};"
        : "+f"(c[0]), "+f"(c[1]), "+f"(c[2]), "+f"(c[3])
        : "r"(a[0]), "r"(a[1]), "r"(a[2]), "r"(a[3]), "r"(b0), "r"(b1));
}
__device__ __forceinline__ void cpa16(uint32_t d, const void* s) {
    asm volatile("cp.async.cg.shared.global [%0], [%1], 16;" :: "r"(d), "l"(s) : "memory");
}
#define CP_COMMIT() asm volatile("cp.async.commit_group;" ::: "memory")

__device__ __forceinline__ uint32_t pkh2(__half a, __half b) {
    __half2 p = __halves2half2(a, b);
    return *reinterpret_cast<uint32_t*>(&p);
}
__device__ __forceinline__ void split2h(float v0, float v1, uint32_t& hw, uint32_t& lw) {
    __half h0 = __float2half_rn(v0);
    __half h1 = __float2half_rn(v1);
    __half l0 = __float2half_rn(v0 - __half2float(h0));
    __half l1 = __float2half_rn(v1 - __half2float(h1));
    hw = pkh2(h0, h1);
    lw = pkh2(l0, l1);
}
__device__ __forceinline__ uint32_t rnd2h(float v0, float v1) {
    return pkh2(__float2half_rn(v0), __float2half_rn(v1));
}

// ---------------- fused one-shot splits + counter zeroing (single launch) -----------
#define BX (NP * DD / 2 / 256)   // 12512
__global__ void split_all_kernel(const float* __restrict__ x,
                                 const float* __restrict__ w1,
                                 const float* __restrict__ w2,
                                 const float* __restrict__ w3) {
    int b = blockIdx.x;
    if (b < BX) {
        int i = b * 256 + threadIdx.x;           // pair index
        float v0 = 0.f, v1 = 0.f;
        if (i * 2 + 1 < NN * DD) { v0 = x[i * 2]; v1 = x[i * 2 + 1]; }
        else if (i * 2 < NN * DD) { v0 = x[i * 2]; }
        uint32_t hw, lw;
        split2h(v0, v1, hw, lw);
        *(uint32_t*)&g_xh[i * 2] = hw;
        *(uint32_t*)&g_xl[i * 2] = lw;
        return;
    }
    b -= BX;
    if (b < 64) {            // w1
        int i = b * 256 + threadIdx.x;
        *(uint32_t*)&g_w1h[i * 2] = rnd2h(w1[i * 2], w1[i * 2 + 1]);
        return;
    }
    b -= 64;
    if (b < 128) {           // w2
        int i = b * 256 + threadIdx.x;
        *(uint32_t*)&g_w2h[i * 2] = rnd2h(w2[i * 2], w2[i * 2 + 1]);
        return;
    }
    b -= 128;
    if (b < 64) {            // w3
        int i = b * 256 + threadIdx.x;
        *(uint32_t*)&g_w3h[i * 2] = rnd2h(w3[i * 2], w3[i * 2 + 1]);
        return;
    }
    b -= 64;
    {                        // zero deg/fill
        int i = b * 256 + threadIdx.x;
        if (i < NN) { g_deg[i] = 0; g_fill[i] = 0; }
    }
}

// -------- combine (blocks 0..HH) + edge histogram (remaining blocks), fused ---------
__global__ void combine_hist_kernel(const float* __restrict__ dec_w1,
                                    const float* __restrict__ msg_w,
                                    const float* __restrict__ msg_b,
                                    const int* __restrict__ ei) {
    if (blockIdx.x >= HH) {
        int e = (blockIdx.x - HH) * 256 + threadIdx.x;
        if (e < EE) {
            int dd = ei[EE + e];
            if (dd >= 0 && dd < NN) atomicAdd(&g_deg[dd], 1);
        }
        return;
    }
    int i = blockIdx.x;     // output row
    int k = threadIdx.x;
    __shared__ float srow[HH];
    __shared__ float wcs[HH];
    srow[k] = dec_w1[i * 2 * HH + k];
    __syncthreads();
    float sum = 0.f;
    #pragma unroll 8
    for (int j = 0; j < HH; j++)
        sum = fmaf(srow[j], msg_w[j * HH + k], sum);
    wcs[k] = sum;

    __shared__ float red[HH];
    red[k] = srow[k] * msg_b[k];
    __syncthreads();

    if (k < 128) {
        *(uint32_t*)&g_bch[i * 2 * HH + 2 * k] = rnd2h(wcs[2 * k], wcs[2 * k + 1]);
    } else {
        int j = 2 * (k - 128);
        *(uint32_t*)&g_bch[i * 2 * HH + HH + j] =
            rnd2h(dec_w1[i * 2 * HH + HH + j], dec_w1[i * 2 * HH + HH + j + 1]);
    }

    for (int off = HH / 2; off > 0; off >>= 1) {
        if (k < off) red[k] += red[k + off];
        __syncthreads();
    }
    if (k == 0) g_v[i] = red[0];
}

// ---------------- scan: block sums, then per-block prefix ----------------
__global__ void scan1_kernel() {
    __shared__ int sm[256];
    int t = threadIdx.x;
    int idx = blockIdx.x * 256 + t;
    sm[t] = (idx < NN) ? g_deg[idx] : 0;
    __syncthreads();
    for (int off = 128; off > 0; off >>= 1) {
        if (t < off) sm[t] += sm[t + off];
        __syncthreads();
    }
    if (t == 0) g_bsum[blockIdx.x] = sm[0];
}
__global__ void scan3_kernel() {
    __shared__ int sm[256];
    int t = threadIdx.x;
    int b = blockIdx.x;
    sm[t] = (t < b) ? g_bsum[t] : 0;
    __syncthreads();
    for (int off = 128; off > 0; off >>= 1) {
        if (t < off) sm[t] += sm[t + off];
        __syncthreads();
    }
    int blockoff = sm[0];
    __syncthreads();
    int idx = b * 256 + t;
    int v = (idx < NN) ? g_deg[idx] : 0;
    sm[t] = v;
    __syncthreads();
    for (int off = 1; off < 256; off <<= 1) {
        int u = (t >= off) ? sm[t - off] : 0;
        __syncthreads();
        sm[t] += u;
        __syncthreads();
    }
    if (idx <= NN) g_rowptr[idx] = blockoff + sm[t] - v;
}
__global__ void scatter_kernel(const int* __restrict__ ei) {
    int e = blockIdx.x * blockDim.x + threadIdx.x;
    if (e < EE) {
        int dd = ei[EE + e];
        if (dd >= 0 && dd < NN) {
            int pos = g_rowptr[dd] + atomicAdd(&g_fill[dd], 1);
            g_esrc[pos] = ei[e];
        }
    }
}

// ------- aggregation: warp per node; reads fp16 hi/lo h, writes fp16 hi/lo agg ------
__global__ void aggregate_kernel() {
    int warp = (blockIdx.x * blockDim.x + threadIdx.x) >> 5;
    int lane = threadIdx.x & 31;
    if (warp >= NN) return;
    int s0 = g_rowptr[warp], s1 = g_rowptr[warp + 1];
    float acc[8] = {0.f, 0.f, 0.f, 0.f, 0.f, 0.f, 0.f, 0.f};
    for (int e = s0; e < s1; e++) {
        size_t rb = (size_t)g_esrc[e] * HH + lane * 8;
        uint4 uh = __ldg((const uint4*)(g_hh + rb));
        uint4 ul = __ldg((const uint4*)(g_hl + rb));
        const __half2* ph = (const __half2*)&uh;
        const __half2* pl = (const __half2*)&ul;
        #pragma unroll
        for (int q = 0; q < 4; q++) {
            float2 fh = __half22float2(ph[q]);
            float2 fl = __half22float2(pl[q]);
            acc[2 * q]     += fh.x + fl.x;
            acc[2 * q + 1] += fh.y + fl.y;
        }
    }
    size_t base = (size_t)warp * HH + lane * 8;
    #pragma unroll
    for (int q = 0; q < 4; q++) {
        uint32_t hw, lw;
        split2h(acc[2 * q], acc[2 * q + 1], hw, lw);
        *(uint32_t*)&g_gh[base + 2 * q] = hw;
        *(uint32_t*)&g_gl[base + 2 * q] = lw;
    }
}

// ====== fp16 2-term tensor GEMM (encoder layers), 3-stage cp.async pipeline =========
// ASEL: 0 = x-split (KA=128), 1 = a-split (KA=256)
// BSEL: 0 = w1, 1 = w2 ; CSEL: 0 = a-split, 1 = h-split
template<int ASEL, int BSEL, int CSEL>
__global__ void __launch_bounds__(256, 1)
mm_gemm(int K, const float* __restrict__ bias, int M)
{
    constexpr int NT = 8;
    constexpr int OFF_AH = 0, OFF_AL = 16384, OFF_B = 32768;
    constexpr int STAGE_BYTES = 65536;
    constexpr int KA = (ASEL == 0) ? DD : HH;

    extern __shared__ char smem[];
    const uint32_t sb = smem_u32(smem);
    const int tid  = threadIdx.x;
    const int wid  = tid >> 5;
    const int lane = tid & 31;
    const int wm   = wid & 1;
    const int wn   = wid >> 1;

    const __half* Bh_ = (BSEL == 0) ? g_w1h : g_w2h;
    const int bm = blockIdx.x * 128;
    const int NC = K / 64;

    auto issue = [&](int c) {
        int kc = c * 64;
        uint32_t base = sb + (uint32_t)(c % 3) * STAGE_BYTES;
        const __half* Ah_ = (ASEL == 0) ? g_xh : g_ah;
        const __half* Al_ = (ASEL == 0) ? g_xl : g_al;
        #pragma unroll
        for (int i = tid; i < 1024; i += 256) {
            int row = i >> 3, unit = i & 7;
            uint32_t sw = SWZ((uint32_t)(row * 128 + unit * 16));
            size_t go = (size_t)(bm + row) * KA + kc + unit * 8;
            cpa16(base + OFF_AH + sw, Ah_ + go);
            cpa16(base + OFF_AL + sw, Al_ + go);
        }
        #pragma unroll
        for (int i = tid; i < 2048; i += 256) {
            int row = i >> 3, unit = i & 7;
            uint32_t sw = SWZ((uint32_t)(row * 128 + unit * 16));
            size_t go = (size_t)row * K + kc + unit * 8;
            cpa16(base + OFF_B + sw, Bh_ + go);
        }
        CP_COMMIT();
    };

    float acc[4][NT][4];
    #pragma unroll
    for (int mg = 0; mg < 4; mg++)
        #pragma unroll
        for (int nt = 0; nt < NT; nt++)
            #pragma unroll
            for (int q = 0; q < 4; q++) acc[mg][nt][q] = 0.f;

    issue(0);
    if (NC > 1) issue(1);
    for (int c = 0; c < NC; c++) {
        if (c + 1 < NC) asm volatile("cp.async.wait_group 1;" ::: "memory");
        else            asm volatile("cp.async.wait_group 0;" ::: "memory");
        __syncthreads();
        if (c + 2 < NC) issue(c + 2);

        uint32_t base = sb + (uint32_t)(c % 3) * STAGE_BYTES;
        #pragma unroll
        for (int kk = 0; kk < 64; kk += 16) {
            uint32_t ah[4][4], al[4][4];
            #pragma unroll
            for (int mg = 0; mg < 4; mg++) {
                int row = wm * 64 + mg * 16 + (lane & 15);
                int bc  = kk * 2 + ((lane >> 4) << 4);
                uint32_t sw = SWZ((uint32_t)(row * 128 + bc));
                ldsm4(ah[mg], base + OFF_AH + sw);
                ldsm4(al[mg], base + OFF_AL + sw);
            }
            uint32_t bh[4][4];
            #pragma unroll
            for (int np = 0; np < 4; np++) {
                int nrow = wn * 64 + np * 16 + ((lane >> 4) << 3) + (lane & 7);
                int bc   = kk * 2 + (((lane >> 3) & 1) << 4);
                uint32_t sw = SWZ((uint32_t)(nrow * 128 + bc));
                ldsm4(bh[np], base + OFF_B + sw);
            }
            #pragma unroll
            for (int mg = 0; mg < 4; mg++)
                #pragma unroll
                for (int nt = 0; nt < NT; nt++) {
                    int np = nt >> 1, hb = (nt & 1) * 2;
                    mma_f16(acc[mg][nt], ah[mg], bh[np][hb], bh[np][hb + 1]);
                    mma_f16(acc[mg][nt], al[mg], bh[np][hb], bh[np][hb + 1]);
                }
        }
    }

    // ---- epilogue: relu, split, store ----
    #pragma unroll
    for (int mg = 0; mg < 4; mg++) {
        int r0 = bm + wm * 64 + mg * 16 + (lane >> 2);
        #pragma unroll
        for (int rr = 0; rr < 2; rr++) {
            int row = r0 + rr * 8;
            if (row >= M) continue;
            #pragma unroll
            for (int nt = 0; nt < NT; nt++) {
                int col = wn * 64 + nt * 8 + (lane & 3) * 2;
                float v0 = fmaxf(acc[mg][nt][rr * 2]     + bias[col],     0.f);
                float v1 = fmaxf(acc[mg][nt][rr * 2 + 1] + bias[col + 1], 0.f);
                size_t off = (size_t)row * HH + col;
                uint32_t hw, lw;
                split2h(v0, v1, hw, lw);
                if (CSEL == 0) {
                    *(uint32_t*)&g_ah[off] = hw;
                    *(uint32_t*)&g_al[off] = lw;
                } else {
                    *(uint32_t*)&g_hh[off] = hw;
                    *(uint32_t*)&g_hl[off] = lw;
                }
            }
        }
    }
}

// ====== fused decoder: dec1 (K=512, dual A, bcat) + in-block dec2 (K=256, w3) =======
// After dec1 mainloop the block holds full 256-wide d rows; dec2 runs from smem.
__global__ void __launch_bounds__(256, 1)
mm_dec_fused(const float* __restrict__ bias1, const float* __restrict__ bias2,
             float* __restrict__ out, int M)
{
    constexpr int OFF_AH = 0, OFF_AL = 16384, OFF_B = 32768;
    constexpr int STAGE_BYTES = 65536;
    constexpr int K = 512, KA = HH;

    extern __shared__ char smem[];
    const uint32_t sb = smem_u32(smem);
    const int tid  = threadIdx.x;
    const int wid  = tid >> 5;
    const int lane = tid & 31;
    const int wm   = wid & 1;
    const int wn   = wid >> 1;
    const int bm   = blockIdx.x * 128;
    const int NC   = K / 64;    // 8

    auto issue = [&](int c) {
        int kc = c * 64;
        uint32_t base = sb + (uint32_t)(c % 3) * STAGE_BYTES;
        const __half* Ah_ = (kc < HH) ? g_gh : g_hh;
        const __half* Al_ = (kc < HH) ? g_gl : g_hl;
        int kcc = (kc < HH) ? kc : kc - HH;
        #pragma unroll
        for (int i = tid; i < 1024; i += 256) {
            int row = i >> 3, unit = i & 7;
            uint32_t sw = SWZ((uint32_t)(row * 128 + unit * 16));
            size_t go = (size_t)(bm + row) * KA + kcc + unit * 8;
            cpa16(base + OFF_AH + sw, Ah_ + go);
            cpa16(base + OFF_AL + sw, Al_ + go);
        }
        #pragma unroll
        for (int i = tid; i < 2048; i += 256) {
            int row = i >> 3, unit = i & 7;
            uint32_t sw = SWZ((uint32_t)(row * 128 + unit * 16));
            size_t go = (size_t)row * K + kc + unit * 8;
            cpa16(base + OFF_B + sw, g_bch + go);
        }
        CP_COMMIT();
    };

    float acc[4][8][4];
    #pragma unroll
    for (int mg = 0; mg < 4; mg++)
        #pragma unroll
        for (int nt = 0; nt < 8; nt++)
            #pragma unroll
            for (int q = 0; q < 4; q++) acc[mg][nt][q] = 0.f;

    issue(0);
    issue(1);
    for (int c = 0; c < NC; c++) {
        if (c + 1 < NC) asm volatile("cp.async.wait_group 1;" ::: "memory");
        else            asm volatile("cp.async.wait_group 0;" ::: "memory");
        __syncthreads();
        if (c + 2 < NC) issue(c + 2);

        uint32_t base = sb + (uint32_t)(c % 3) * STAGE_BYTES;
        #pragma unroll
        for (int kk = 0; kk < 64; kk += 16) {
            uint32_t ah[4][4], al[4][4];
            #pragma unroll
            for (int mg = 0; mg < 4; mg++) {
                int row = wm * 64 + mg * 16 + (lane & 15);
                int bc  = kk * 2 + ((lane >> 4) << 4);
                uint32_t sw = SWZ((uint32_t)(row * 128 + bc));
                ldsm4(ah[mg], base + OFF_AH + sw);
                ldsm4(al[mg], base + OFF_AL + sw);
            }
            uint32_t bh[4][4];
            #pragma unroll
            for (int np = 0; np < 4; np++) {
                int nrow = wn * 64 + np * 16 + ((lane >> 4) << 3) + (lane & 7);
                int bc   = kk * 2 + (((lane >> 3) & 1) << 4);
                uint32_t sw = SWZ((uint32_t)(nrow * 128 + bc));
                ldsm4(bh[np], base + OFF_B + sw);
            }
            #pragma unroll
            for (int mg = 0; mg < 4; mg++)
                #pragma unroll
                for (int nt = 0; nt < 8; nt++) {
                    int np = nt >> 1, hb = (nt & 1) * 2;
                    mma_f16(acc[mg][nt], ah[mg], bh[np][hb], bh[np][hb + 1]);
                    mma_f16(acc[mg][nt], al[mg], bh[np][hb], bh[np][hb + 1]);
                }
        }
    }

    // ==== fused dec2 ====
    __syncthreads();   // all warps done reading stage buffers

    // stage w3 [128 x 256] fp16 into buffer 2 region as 4 chunks of 16KB
    #pragma unroll
    for (int i = tid; i < 4096; i += 256) {
        int chunk = i >> 10;
        int row   = (i >> 3) & 127;
        int unit  = i & 7;
        uint32_t sw = SWZ((uint32_t)(row * 128 + unit * 16));
        cpa16(sb + 2 * STAGE_BYTES + chunk * 16384 + sw,
              g_w3h + (size_t)row * 256 + chunk * 64 + unit * 8);
    }
    CP_COMMIT();

    // write d (relu(acc + bias1 + deg*v)) as fp16 hi/lo into buffers 0/1 (chunked)
    #pragma unroll
    for (int mg = 0; mg < 4; mg++) {
        int r0 = wm * 64 + mg * 16 + (lane >> 2);
        #pragma unroll
        for (int rr = 0; rr < 2; rr++) {
            int row  = r0 + rr * 8;
            int grow = bm + row;
            float dg = (grow < M) ? (float)g_deg[grow] : 0.f;
            #pragma unroll
            for (int nt = 0; nt < 8; nt++) {
                int col = wn * 64 + nt * 8 + (lane & 3) * 2;   // 0..255
                float v0 = fmaxf(acc[mg][nt][rr * 2]     + bias1[col]     + dg * g_v[col],     0.f);
                float v1 = fmaxf(acc[mg][nt][rr * 2 + 1] + bias1[col + 1] + dg * g_v[col + 1], 0.f);
                uint32_t hw, lw;
                split2h(v0, v1, hw, lw);
                int chunk = col >> 6;          // == wn
                int c     = col & 63;
                uint32_t sw = SWZ((uint32_t)(row * 128 + c * 2));
                *(uint32_t*)(smem + chunk * 16384 + sw)               = hw;  // d_h (buf0)
                *(uint32_t*)(smem + STAGE_BYTES + chunk * 16384 + sw) = lw;  // d_l (buf1)
            }
        }
    }
    asm volatile("cp.async.wait_group 0;" ::: "memory");
    __syncthreads();

    // in-block GEMM: out[128 x 128] = tanh(d @ w3^T + bias2), 2-term, K=256
    float acc2[4][4][4];
    #pragma unroll
    for (int mg = 0; mg < 4; mg++)
        #pragma unroll
        for (int nt = 0; nt < 4; nt++)
            #pragma unroll
            for (int q = 0; q < 4; q++) acc2[mg][nt][q] = 0.f;

    #pragma unroll
    for (int kc = 0; kc < 4; kc++) {
        #pragma unroll
        for (int kk = 0; kk < 64; kk += 16) {
            uint32_t ah2[4][4], al2[4][4];
            #pragma unroll
            for (int mg = 0; mg < 4; mg++) {
                int row = wm * 64 + mg * 16 + (lane & 15);
                int bc  = kk * 2 + ((lane >> 4) << 4);
                uint32_t sw = SWZ((uint32_t)(row * 128 + bc));
                ldsm4(ah2[mg], sb + kc * 16384 + sw);
                ldsm4(al2[mg], sb + STAGE_BYTES + kc * 16384 + sw);
            }
            uint32_t bh2[2][4];
            #pragma unroll
            for (int np = 0; np < 2; np++) {
                int nrow = wn * 32 + np * 16 + ((lane >> 4) << 3) + (lane & 7);
                int bc   = kk * 2 + (((lane >> 3) & 1) << 4);
                uint32_t sw = SWZ((uint32_t)(nrow * 128 + bc));
                ldsm4(bh2[np], sb + 2 * STAGE_BYTES + kc * 16384 + sw);
            }
            #pragma unroll
            for (int mg = 0; mg < 4; mg++)
                #pragma unroll
                for (int nt = 0; nt < 4; nt++) {
                    int np = nt >> 1, hb = (nt & 1) * 2;
                    mma_f16(acc2[mg][nt], ah2[mg], bh2[np][hb], bh2[np][hb + 1]);
                    mma_f16(acc2[mg][nt], al2[mg], bh2[np][hb], bh2[np][hb + 1]);
                }
        }
    }

    // epilogue: tanh + store fp32 output
    #pragma unroll
    for (int mg = 0; mg < 4; mg++) {
        int r0 = bm + wm * 64 + mg * 16 + (lane >> 2);
        #pragma unroll
        for (int rr = 0; rr < 2; rr++) {
            int row = r0 + rr * 8;
            if (row >= M) continue;
            #pragma unroll
            for (int nt = 0; nt < 4; nt++) {
                int col = wn * 32 + nt * 8 + (lane & 3) * 2;
                float v0 = tanhf(acc2[mg][nt][rr * 2]     + bias2[col]);
                float v1 = tanhf(acc2[mg][nt][rr * 2 + 1] + bias2[col + 1]);
                *(float2*)(out + (size_t)row * DD + col) = make_float2(v0, v1);
            }
        }
    }
}

// ---------------- launch: fork CSR chain onto side stream (capture-safe) ------------
extern "C" void kernel_launch(void* const* d_in, const int* in_sizes, int n_in,
                              void* d_out, int out_size) {
    (void)in_sizes; (void)n_in; (void)out_size;
    const float* x      = (const float*)d_in[0];
    const int*   ei     = (const int*)d_in[1];
    const float* enc_w1 = (const float*)d_in[3];
    const float* enc_b1 = (const float*)d_in[4];
    const float* enc_w2 = (const float*)d_in[5];
    const float* enc_b2 = (const float*)d_in[6];
    const float* msg_w  = (const float*)d_in[7];
    const float* msg_b  = (const float*)d_in[8];
    const float* dec_w1 = (const float*)d_in[9];
    const float* dec_b1 = (const float*)d_in[10];
    const float* dec_w2 = (const float*)d_in[11];
    const float* dec_b2 = (const float*)d_in[12];
    float* out = (float*)d_out;

    const int SM = 3 * 65536;   // 192KB
    cudaFuncSetAttribute(mm_gemm<0, 0, 0>, cudaFuncAttributeMaxDynamicSharedMemorySize, SM);
    cudaFuncSetAttribute(mm_gemm<1, 1, 1>, cudaFuncAttributeMaxDynamicSharedMemorySize, SM);
    cudaFuncSetAttribute(mm_dec_fused,     cudaFuncAttributeMaxDynamicSharedMemorySize, SM);

    // side stream + events (created per call; kernel_launch runs only for
    // correctness + the single capture pass; never destroyed mid-capture)
    cudaStream_t s2;
    cudaStreamCreateWithFlags(&s2, cudaStreamNonBlocking);
    cudaEvent_t evFork, evJoin;
    cudaEventCreateWithFlags(&evFork, cudaEventDisableTiming);
    cudaEventCreateWithFlags(&evJoin, cudaEventDisableTiming);

    // main stream: splits (also zeroes deg/fill)
    split_all_kernel<<<BX + 64 + 128 + 64 + 196, 256>>>(x, enc_w1, enc_w2, dec_w2);
    cudaEventRecord(evFork, 0);

    // side stream: CSR chain + weight-combine, overlapped with encoder GEMMs
    cudaStreamWaitEvent(s2, evFork, 0);
    combine_hist_kernel<<<HH + (EE + 255) / 256, 256, 0, s2>>>(dec_w1, msg_w, msg_b, ei);
    scan1_kernel<<<NB, 256, 0, s2>>>();
    scan3_kernel<<<NB, 256, 0, s2>>>();
    scatter_kernel<<<(EE + 255) / 256, 256, 0, s2>>>(ei);
    cudaEventRecord(evJoin, s2);

    const int MT = (NN + 127) / 128;   // 391 M-tiles

    // main stream: encoder GEMMs run concurrently with the CSR chain
    mm_gemm<0, 0, 0><<<MT, 256, SM>>>(DD, enc_b1, NN);   // enc1: h1-split
    mm_gemm<1, 1, 1><<<MT, 256, SM>>>(HH, enc_b2, NN);   // enc2: h-split

    // join: aggregate needs scatter (s2) + enc2 (main)
    cudaStreamWaitEvent(0, evJoin, 0);
    aggregate_kernel<<<(NN * 32 + 255) / 256, 256>>>();
    // fused dec1+dec2: out = tanh(relu(agg@Wc^T + h@w1b^T + deg*v + b1) @ w3^T + b2)
    mm_dec_fused<<<MT, 256, SM>>>(dec_b1, dec_b2, out, NN);
}